// round 3
// baseline (speedup 1.0000x reference)
#include <cuda_runtime.h>
#include <math.h>
#include <stdint.h>

// ---------------------------------------------------------------------------
// Problem constants (fixed by the reference)
// ---------------------------------------------------------------------------
#define NA        4096
#define ED        256      // EMBED_DIMS
#define NG        8        // NUM_GROUPS
#define GD        32       // GROUP_DIMS
#define NL        4        // NUM_LEVELS
#define NC        6        // NUM_CAMS
#define NPT       13       // NUM_PTS (7 fixed + 6 learnable)
#define NSAMP     312      // NC*NL*NPT
#define NWTS      2496     // NSAMP*NG

// level dims
__constant__ int   c_LW[4] = {176, 88, 44, 22};
__constant__ int   c_LH[4] = {64, 32, 16, 8};
__constant__ unsigned c_LB[4] = {0u, 17301504u, 21626880u, 22708224u};

__constant__ float c_fix[21] = {
    0.f,0.f,0.f,  0.45f,0.f,0.f,  -0.45f,0.f,0.f,
    0.f,0.45f,0.f, 0.f,-0.45f,0.f, 0.f,0.f,0.45f, 0.f,0.f,-0.45f
};

// ---------------------------------------------------------------------------
// Scratch (static __device__ — no allocations allowed).
// NOTE: these symbols must ONLY be referenced from device code. Taking their
// address in host code yields the host shadow address (and GB300's ATS makes
// that silently dereferenceable => wrong results, no fault).
// ---------------------------------------------------------------------------
__device__ float g_nhwc[22978560];          // all 4 levels, NHWC (cam,h,w,c)
__device__ float g_logits[NA * NWTS];       // weight logits (softmaxed in agg)
__device__ float g_p2d[NA * NPT * NC * 2];  // projected points
__device__ float g_feats[NA * ED];          // aggregated features

// ---------------------------------------------------------------------------
// 1) CHW -> HWC transpose (per level). src: [6][256][HW] -> g_nhwc+base: [6][HW][256]
// ---------------------------------------------------------------------------
__global__ void transpose_chw_hwc(const float* __restrict__ src, unsigned dst_base, int HW) {
    __shared__ float tile[32][33];
    int cam = blockIdx.z;
    int hw0 = blockIdx.x * 32;
    int c0  = blockIdx.y * 32;
    const float* s = src + (size_t)cam * ED * HW;
    float* d = g_nhwc + dst_base + (size_t)cam * HW * ED;
    int tx = threadIdx.x, ty = threadIdx.y;
#pragma unroll
    for (int i = 0; i < 32; i += 8) {
        int c  = c0 + ty + i;
        int hw = hw0 + tx;
        float v = (hw < HW) ? s[(size_t)c * HW + hw] : 0.f;
        tile[ty + i][tx] = v;
    }
    __syncthreads();
#pragma unroll
    for (int i = 0; i < 32; i += 8) {
        int hw = hw0 + ty + i;
        int c  = c0 + tx;
        if (hw < HW) d[(size_t)hw * ED + c] = tile[tx][ty + i];
    }
}

// ---------------------------------------------------------------------------
// 2) Per-anchor setup: learnable points, rotation, projection -> g_p2d
//    One block (128 threads) per anchor.
// ---------------------------------------------------------------------------
__global__ void __launch_bounds__(128) setup_kernel(
    const float* __restrict__ inst, const float* __restrict__ anchor,
    const float* __restrict__ proj, const float* __restrict__ wh,
    const float* __restrict__ Wl, const float* __restrict__ bl)
{
    int a = blockIdx.x;
    int tid = threadIdx.x;
    __shared__ float sif[ED];
    __shared__ float sscale[NPT * 3];
    __shared__ float skp[NPT * 3];
    __shared__ float sR[9];
    __shared__ float sts[6];

    const float* f = inst + (size_t)a * ED;
    sif[tid]       = f[tid];
    sif[tid + 128] = f[tid + 128];
    if (tid < 21) sscale[tid] = c_fix[tid];
    __syncthreads();

    const float* an = anchor + (size_t)a * 11;

    if (tid < 18) {
        float acc = bl[tid];
#pragma unroll 8
        for (int i = 0; i < ED; i++) acc = fmaf(sif[i], Wl[i * 18 + tid], acc);
        acc = fminf(fmaxf(acc, -9.21f), 9.21f);
        float sg = 1.f / (1.f + expf(-acc));
        sscale[21 + tid] = sg - 0.5f;
    }
    if (tid == 32) {
        float t0 = an[0], t1 = an[1], t2 = an[2];
        float s0 = an[3], s1 = an[4], s2 = an[5];
        float qw = an[6], qx = an[7], qy = an[8], qz = an[9];
        float inv = rsqrtf(qw*qw + qx*qx + qy*qy + qz*qz);
        qw *= inv; qx *= inv; qy *= inv; qz *= inv;
        float R00 = 1.f - 2.f*(qy*qy + qz*qz), R01 = 2.f*(qx*qy - qw*qz), R02 = 2.f*(qx*qz + qw*qy);
        float R10 = 2.f*(qx*qy + qw*qz), R11 = 1.f - 2.f*(qx*qx + qz*qz), R12 = 2.f*(qy*qz - qw*qx);
        float R20 = 2.f*(qx*qz - qw*qy), R21 = 2.f*(qy*qz + qw*qx), R22 = 1.f - 2.f*(qx*qx + qy*qy);
        // Rt[i][j] = R[j][i]
        sR[0] = R00; sR[1] = R10; sR[2] = R20;
        sR[3] = R01; sR[4] = R11; sR[5] = R21;
        sR[6] = R02; sR[7] = R12; sR[8] = R22;
        sts[0] = t0; sts[1] = t1; sts[2] = t2;
        sts[3] = s0; sts[4] = s1; sts[5] = s2;
    }
    __syncthreads();
    if (tid < NPT) {
        float v0 = sscale[tid*3+0] * sts[3];
        float v1 = sscale[tid*3+1] * sts[4];
        float v2 = sscale[tid*3+2] * sts[5];
        skp[tid*3+0] = sR[0]*v0 + sR[1]*v1 + sR[2]*v2 + sts[0];
        skp[tid*3+1] = sR[3]*v0 + sR[4]*v1 + sR[5]*v2 + sts[1];
        skp[tid*3+2] = sR[6]*v0 + sR[7]*v1 + sR[8]*v2 + sts[2];
    }
    __syncthreads();
    if (tid < NPT * NC) {
        int pt = tid / NC, cam = tid % NC;
        float x = skp[pt*3+0], y = skp[pt*3+1], z = skp[pt*3+2];
        const float* P = proj + cam * 16;
        float px = P[0]*x + P[1]*y + P[2]*z  + P[3];
        float py = P[4]*x + P[5]*y + P[6]*z  + P[7];
        float pz = P[8]*x + P[9]*y + P[10]*z + P[11];
        pz = fmaxf(pz, 1e-5f);
        float u = (px / pz) / wh[cam*2+0];
        float v = (py / pz) / wh[cam*2+1];
        u = fminf(fmaxf(u, 0.f), 0.9999f);
        v = fminf(fmaxf(v, 0.f), 0.9999f);
        g_p2d[((size_t)a * (NPT*NC) + tid) * 2 + 0] = u;
        g_p2d[((size_t)a * (NPT*NC) + tid) * 2 + 1] = v;
    }
}

// ---------------------------------------------------------------------------
// 3/5) Tiled SGEMM: C[M,N] = A[M,K] @ B[K,N] (+ bias[n]) (+ residual[m,n])
//      BM=128 BN=64 BK=16, 256 threads, 8x4 microtile.
//      mode 1: C := g_logits (resolved device-side)
//      mode 2: A := g_feats  (resolved device-side)
// ---------------------------------------------------------------------------
__global__ void __launch_bounds__(256) sgemm_kernel(
    const float* __restrict__ A, const float* __restrict__ B, float* __restrict__ C,
    int M, int N, int K, const float* __restrict__ bias, const float* __restrict__ res,
    int mode)
{
    if (mode == 1) C = g_logits;      // device-side symbol resolution
    if (mode == 2) A = g_feats;

    const int BM = 128, BN = 64, BK = 16;
    __shared__ float As[BK][BM];
    __shared__ float Bs[BK][BN];
    int tid = threadIdx.x;
    int tx = tid & 15, ty = tid >> 4;
    int m0 = blockIdx.y * BM, n0 = blockIdx.x * BN;

    float acc[8][4];
#pragma unroll
    for (int x = 0; x < 8; x++)
#pragma unroll
        for (int y = 0; y < 4; y++) acc[x][y] = 0.f;

    for (int k0 = 0; k0 < K; k0 += BK) {
#pragma unroll
        for (int i = 0; i < 8; i++) {
            int e = tid + i * 256;
            int m = e >> 4, kk = e & 15;
            As[kk][m] = A[(size_t)(m0 + m) * K + k0 + kk];
        }
#pragma unroll
        for (int i = 0; i < 4; i++) {
            int e = tid + i * 256;
            int kk = e >> 6, n = e & 63;
            Bs[kk][n] = B[(size_t)(k0 + kk) * N + n0 + n];
        }
        __syncthreads();
#pragma unroll
        for (int kk = 0; kk < BK; kk++) {
            float av[8], bv[4];
#pragma unroll
            for (int j = 0; j < 8; j++) av[j] = As[kk][ty * 8 + j];
#pragma unroll
            for (int j = 0; j < 4; j++) bv[j] = Bs[kk][tx * 4 + j];
#pragma unroll
            for (int x = 0; x < 8; x++)
#pragma unroll
                for (int y = 0; y < 4; y++)
                    acc[x][y] = fmaf(av[x], bv[y], acc[x][y]);
        }
        __syncthreads();
    }
#pragma unroll
    for (int x = 0; x < 8; x++) {
        int m = m0 + ty * 8 + x;
#pragma unroll
        for (int y = 0; y < 4; y++) {
            int n = n0 + tx * 4 + y;
            float v = acc[x][y];
            if (bias) v += bias[n];
            if (res)  v += res[(size_t)m * N + n];
            C[(size_t)m * N + n] = v;
        }
    }
}

// ---------------------------------------------------------------------------
// 4) Fused softmax + bilinear deformable aggregation.
//    One block (256 threads = one channel each) per anchor.
// ---------------------------------------------------------------------------
__global__ void __launch_bounds__(256) agg_kernel() {
    int a = blockIdx.x;
    int tid = threadIdx.x;
    int lane = tid & 31, warp = tid >> 5;

    __shared__ float  sw[NWTS];        // logits -> softmaxed weights
    __shared__ float2 sp[NPT * NC];    // p2d
    __shared__ uint4  soff[NSAMP];     // 4 corner offsets (elements)
    __shared__ float4 scw[NSAMP];      // 4 corner bilinear weights

    const float* lrow = g_logits + (size_t)a * NWTS;
    for (int i = tid; i < NWTS; i += 256) sw[i] = lrow[i];
    if (tid < NPT * NC) sp[tid] = ((const float2*)g_p2d)[(size_t)a * (NPT*NC) + tid];
    __syncthreads();

    // per-group softmax over 312 entries (warp g handles group g; 8 warps = 8 groups)
    {
        int g = warp;
        float m = -1e30f;
        for (int i = lane; i < NSAMP; i += 32) m = fmaxf(m, sw[i * NG + g]);
#pragma unroll
        for (int o = 16; o > 0; o >>= 1) m = fmaxf(m, __shfl_xor_sync(0xffffffffu, m, o));
        float ssum = 0.f;
        for (int i = lane; i < NSAMP; i += 32) {
            float e = expf(sw[i * NG + g] - m);
            sw[i * NG + g] = e;
            ssum += e;
        }
#pragma unroll
        for (int o = 16; o > 0; o >>= 1) ssum += __shfl_xor_sync(0xffffffffu, ssum, o);
        float inv = 1.f / ssum;
        for (int i = lane; i < NSAMP; i += 32) sw[i * NG + g] *= inv;
    }
    __syncthreads();

    // precompute per-sample gather metadata
    for (int s = tid; s < NSAMP; s += 256) {
        int cam = s / (NL * NPT);
        int rr  = s % (NL * NPT);
        int lvl = rr / NPT;
        int pt  = rr % NPT;
        float2 p = sp[pt * NC + cam];
        int W = c_LW[lvl], H = c_LH[lvl];
        float x = p.x * (float)W - 0.5f;
        float y = p.y * (float)H - 0.5f;
        float xf = floorf(x), yf = floorf(y);
        float wx = x - xf, wy = y - yf;
        int x0 = (int)xf, y0 = (int)yf;
        int x1 = x0 + 1, y1 = y0 + 1;
        bool vx0 = (x0 >= 0) & (x0 < W);
        bool vx1 = (x1 >= 0) & (x1 < W);
        bool vy0 = (y0 >= 0) & (y0 < H);
        bool vy1 = (y1 >= 0) & (y1 < H);
        float w00 = (vx0 && vy0) ? (1.f - wx) * (1.f - wy) : 0.f;
        float w01 = (vx1 && vy0) ? wx * (1.f - wy) : 0.f;
        float w10 = (vx0 && vy1) ? (1.f - wx) * wy : 0.f;
        float w11 = (vx1 && vy1) ? wx * wy : 0.f;
        int x0c = min(max(x0, 0), W - 1), x1c = min(max(x1, 0), W - 1);
        int y0c = min(max(y0, 0), H - 1), y1c = min(max(y1, 0), H - 1);
        unsigned lb = c_LB[lvl];
        unsigned rowb = (unsigned)(cam * H);
        unsigned o00 = lb + ((rowb + (unsigned)y0c) * (unsigned)W + (unsigned)x0c) * 256u;
        unsigned o01 = lb + ((rowb + (unsigned)y0c) * (unsigned)W + (unsigned)x1c) * 256u;
        unsigned o10 = lb + ((rowb + (unsigned)y1c) * (unsigned)W + (unsigned)x0c) * 256u;
        unsigned o11 = lb + ((rowb + (unsigned)y1c) * (unsigned)W + (unsigned)x1c) * 256u;
        soff[s] = make_uint4(o00, o01, o10, o11);
        scw[s]  = make_float4(w00, w01, w10, w11);
    }
    __syncthreads();

    int g = tid >> 5;  // group of this channel
    float acc = 0.f;
    const float* __restrict__ F = g_nhwc;
#pragma unroll 4
    for (int s = 0; s < NSAMP; s++) {
        uint4 o  = soff[s];
        float4 c = scw[s];
        float v = c.x * __ldg(F + o.x + tid)
                + c.y * __ldg(F + o.y + tid)
                + c.z * __ldg(F + o.z + tid)
                + c.w * __ldg(F + o.w + tid);
        acc = fmaf(sw[s * NG + g], v, acc);
    }
    g_feats[(size_t)a * ED + tid] = acc;
}

// ---------------------------------------------------------------------------
// launch — inputs bound by unique element counts (order-proof)
// ---------------------------------------------------------------------------
extern "C" void kernel_launch(void* const* d_in, const int* in_sizes, int n_in,
                              void* d_out, int out_size) {
    const float* inst = 0; const float* anchor = 0;
    const float* feat[4] = {0,0,0,0};
    const float* proj = 0; const float* wh = 0;
    const float* Wl = 0; const float* bl = 0;
    const float* Ww = 0; const float* bw = 0;
    const float* Wo = 0; const float* bo = 0;

    for (int i = 0; i < n_in; i++) {
        const float* p = (const float*)d_in[i];
        switch (in_sizes[i]) {
            case 1048576:  inst    = p; break;  // (1,4096,256)
            case 45056:    anchor  = p; break;  // (1,4096,11)
            case 17301504: feat[0] = p; break;
            case 4325376:  feat[1] = p; break;
            case 1081344:  feat[2] = p; break;
            case 270336:   feat[3] = p; break;
            case 96:       proj    = p; break;  // (1,6,4,4)
            case 12:       wh      = p; break;  // (1,6,2)
            case 4608:     Wl      = p; break;  // (256,18)
            case 18:       bl      = p; break;
            case 638976:   Ww      = p; break;  // (256,2496)
            case 2496:     bw      = p; break;
            case 65536:    Wo      = p; break;  // (256,256)
            case 256:      bo      = p; break;
            default: break;                      // pts3d (300000) unused
        }
    }
    float* out = (float*)d_out;

    // 1) transposes
    const int HWs[4] = {64 * 176, 32 * 88, 16 * 44, 8 * 22};
    const unsigned LBs[4] = {0u, 17301504u, 21626880u, 22708224u};
    for (int l = 0; l < 4; l++) {
        dim3 grid((HWs[l] + 31) / 32, ED / 32, NC);
        dim3 block(32, 8);
        transpose_chw_hwc<<<grid, block>>>(feat[l], LBs[l], HWs[l]);
    }

    // 2) per-anchor setup
    setup_kernel<<<NA, 128>>>(inst, anchor, proj, wh, Wl, bl);

    // 3) weight logits GEMM: (4096x256) @ (256x2496) -> g_logits (mode 1)
    {
        dim3 grid(NWTS / 64, NA / 128);
        sgemm_kernel<<<grid, 256>>>(inst, Ww, nullptr, NA, NWTS, ED, bw, nullptr, 1);
    }

    // 4) fused softmax + aggregation
    agg_kernel<<<NA, 256>>>();

    // 5) output GEMM: g_feats (mode 2) @ (256x256) + b_out + inst -> d_out
    {
        dim3 grid(ED / 64, NA / 128);
        sgemm_kernel<<<grid, 256>>>(nullptr, Wo, out, NA, ED, ED, bo, inst, 2);
    }
}

// round 4
// speedup vs baseline: 1.3580x; 1.3580x over previous
#include <cuda_runtime.h>
#include <cuda_fp16.h>
#include <math.h>
#include <stdint.h>

// ---------------------------------------------------------------------------
// Problem constants (fixed by the reference)
// ---------------------------------------------------------------------------
#define NA        4096
#define ED        256      // EMBED_DIMS
#define NG        8        // NUM_GROUPS
#define GD        32       // GROUP_DIMS
#define NL        4        // NUM_LEVELS
#define NC        6        // NUM_CAMS
#define NPT       13       // NUM_PTS (7 fixed + 6 learnable)
#define NSAMP     312      // NC*NL*NPT
#define NWTS      2496     // NSAMP*NG

// level dims
__constant__ int   c_LW[4] = {176, 88, 44, 22};
__constant__ int   c_LH[4] = {64, 32, 16, 8};
__constant__ unsigned c_LB[4] = {0u, 17301504u, 21626880u, 22708224u};

__constant__ float c_fix[21] = {
    0.f,0.f,0.f,  0.45f,0.f,0.f,  -0.45f,0.f,0.f,
    0.f,0.45f,0.f, 0.f,-0.45f,0.f, 0.f,0.f,0.45f, 0.f,0.f,-0.45f
};

// ---------------------------------------------------------------------------
// Scratch (static __device__ — device-code references ONLY; host-side address
// of a __device__ symbol is the host shadow and silently "works" via ATS).
// ---------------------------------------------------------------------------
__device__ __half g_nhwc16[22978560];       // all 4 levels, NHWC (cam,h,w,c), fp16
__device__ float  g_logits[NA * NWTS];      // weight logits (softmaxed in agg)
__device__ float  g_p2d[NA * NPT * NC * 2]; // projected points
__device__ float  g_feats[NA * ED];         // aggregated features

// ---------------------------------------------------------------------------
// 1) CHW -> HWC transpose + fp32->fp16 convert (per level).
//    src: [6][256][HW] -> g_nhwc16+base: [6][HW][256]
// ---------------------------------------------------------------------------
__global__ void transpose_chw_hwc(const float* __restrict__ src, unsigned dst_base, int HW) {
    __shared__ float tile[32][33];
    int cam = blockIdx.z;
    int hw0 = blockIdx.x * 32;
    int c0  = blockIdx.y * 32;
    const float* s = src + (size_t)cam * ED * HW;
    __half* d = g_nhwc16 + dst_base + (size_t)cam * HW * ED;
    int tx = threadIdx.x, ty = threadIdx.y;
#pragma unroll
    for (int i = 0; i < 32; i += 8) {
        int c  = c0 + ty + i;
        int hw = hw0 + tx;
        float v = (hw < HW) ? s[(size_t)c * HW + hw] : 0.f;
        tile[ty + i][tx] = v;
    }
    __syncthreads();
#pragma unroll
    for (int i = 0; i < 32; i += 8) {
        int hw = hw0 + ty + i;
        int c  = c0 + tx;
        if (hw < HW) d[(size_t)hw * ED + c] = __float2half(tile[tx][ty + i]);
    }
}

// ---------------------------------------------------------------------------
// 2) Per-anchor setup: learnable points, rotation, projection -> g_p2d
// ---------------------------------------------------------------------------
__global__ void __launch_bounds__(128) setup_kernel(
    const float* __restrict__ inst, const float* __restrict__ anchor,
    const float* __restrict__ proj, const float* __restrict__ wh,
    const float* __restrict__ Wl, const float* __restrict__ bl)
{
    int a = blockIdx.x;
    int tid = threadIdx.x;
    __shared__ float sif[ED];
    __shared__ float sscale[NPT * 3];
    __shared__ float skp[NPT * 3];
    __shared__ float sR[9];
    __shared__ float sts[6];

    const float* f = inst + (size_t)a * ED;
    sif[tid]       = f[tid];
    sif[tid + 128] = f[tid + 128];
    if (tid < 21) sscale[tid] = c_fix[tid];
    __syncthreads();

    const float* an = anchor + (size_t)a * 11;

    if (tid < 18) {
        float acc = bl[tid];
#pragma unroll 8
        for (int i = 0; i < ED; i++) acc = fmaf(sif[i], Wl[i * 18 + tid], acc);
        acc = fminf(fmaxf(acc, -9.21f), 9.21f);
        float sg = 1.f / (1.f + expf(-acc));
        sscale[21 + tid] = sg - 0.5f;
    }
    if (tid == 32) {
        float t0 = an[0], t1 = an[1], t2 = an[2];
        float s0 = an[3], s1 = an[4], s2 = an[5];
        float qw = an[6], qx = an[7], qy = an[8], qz = an[9];
        float inv = rsqrtf(qw*qw + qx*qx + qy*qy + qz*qz);
        qw *= inv; qx *= inv; qy *= inv; qz *= inv;
        float R00 = 1.f - 2.f*(qy*qy + qz*qz), R01 = 2.f*(qx*qy - qw*qz), R02 = 2.f*(qx*qz + qw*qy);
        float R10 = 2.f*(qx*qy + qw*qz), R11 = 1.f - 2.f*(qx*qx + qz*qz), R12 = 2.f*(qy*qz - qw*qx);
        float R20 = 2.f*(qx*qz - qw*qy), R21 = 2.f*(qy*qz + qw*qx), R22 = 1.f - 2.f*(qx*qx + qy*qy);
        sR[0] = R00; sR[1] = R10; sR[2] = R20;
        sR[3] = R01; sR[4] = R11; sR[5] = R21;
        sR[6] = R02; sR[7] = R12; sR[8] = R22;
        sts[0] = t0; sts[1] = t1; sts[2] = t2;
        sts[3] = s0; sts[4] = s1; sts[5] = s2;
    }
    __syncthreads();
    if (tid < NPT) {
        float v0 = sscale[tid*3+0] * sts[3];
        float v1 = sscale[tid*3+1] * sts[4];
        float v2 = sscale[tid*3+2] * sts[5];
        skp[tid*3+0] = sR[0]*v0 + sR[1]*v1 + sR[2]*v2 + sts[0];
        skp[tid*3+1] = sR[3]*v0 + sR[4]*v1 + sR[5]*v2 + sts[1];
        skp[tid*3+2] = sR[6]*v0 + sR[7]*v1 + sR[8]*v2 + sts[2];
    }
    __syncthreads();
    if (tid < NPT * NC) {
        int pt = tid / NC, cam = tid % NC;
        float x = skp[pt*3+0], y = skp[pt*3+1], z = skp[pt*3+2];
        const float* P = proj + cam * 16;
        float px = P[0]*x + P[1]*y + P[2]*z  + P[3];
        float py = P[4]*x + P[5]*y + P[6]*z  + P[7];
        float pz = P[8]*x + P[9]*y + P[10]*z + P[11];
        pz = fmaxf(pz, 1e-5f);
        float u = (px / pz) / wh[cam*2+0];
        float v = (py / pz) / wh[cam*2+1];
        u = fminf(fmaxf(u, 0.f), 0.9999f);
        v = fminf(fmaxf(v, 0.f), 0.9999f);
        g_p2d[((size_t)a * (NPT*NC) + tid) * 2 + 0] = u;
        g_p2d[((size_t)a * (NPT*NC) + tid) * 2 + 1] = v;
    }
}

// ---------------------------------------------------------------------------
// 3/5) Tiled SGEMM using packed fma.rn.f32x2 (2x FFMA throughput).
//      C[M,N] = A[M,K] @ B[K,N] (+ bias[n]) (+ res[m,n])
//      BM=128 BN=64 BK=16, 256 threads, 8x4 microtile (as 8x2 f32x2 pairs).
//      mode 1: C := g_logits   mode 2: A := g_feats   (device-side symbols)
// ---------------------------------------------------------------------------
__global__ void __launch_bounds__(256) sgemm_kernel(
    const float* __restrict__ A, const float* __restrict__ B, float* __restrict__ C,
    int M, int N, int K, const float* __restrict__ bias, const float* __restrict__ res,
    int mode)
{
    if (mode == 1) C = g_logits;
    if (mode == 2) A = g_feats;

    const int BM = 128, BN = 64, BK = 16;
    __shared__ float2 Asd[BK][BM + 2];   // A value duplicated into both lanes; +2 pad (16B-aligned rows, conflict-light)
    __shared__ float  Bs[BK][BN];
    int tid = threadIdx.x;
    int tx = tid & 15, ty = tid >> 4;
    int m0 = blockIdx.y * BM, n0 = blockIdx.x * BN;

    unsigned long long acc[8][2];
#pragma unroll
    for (int x = 0; x < 8; x++) { acc[x][0] = 0ull; acc[x][1] = 0ull; }

    for (int k0 = 0; k0 < K; k0 += BK) {
#pragma unroll
        for (int i = 0; i < 8; i++) {
            int e = tid + i * 256;
            int m = e >> 4, kk = e & 15;
            float v = A[(size_t)(m0 + m) * K + k0 + kk];
            Asd[kk][m] = make_float2(v, v);
        }
#pragma unroll
        for (int i = 0; i < 4; i++) {
            int e = tid + i * 256;
            int kk = e >> 6, n = e & 63;
            Bs[kk][n] = B[(size_t)(k0 + kk) * N + n0 + n];
        }
        __syncthreads();
#pragma unroll
        for (int kk = 0; kk < BK; kk++) {
            unsigned long long av[8], bv[2];
            const ulonglong2* ap = (const ulonglong2*)&Asd[kk][ty * 8];
            ulonglong2 t;
            t = ap[0]; av[0] = t.x; av[1] = t.y;
            t = ap[1]; av[2] = t.x; av[3] = t.y;
            t = ap[2]; av[4] = t.x; av[5] = t.y;
            t = ap[3]; av[6] = t.x; av[7] = t.y;
            ulonglong2 bq = *(const ulonglong2*)&Bs[kk][tx * 4];
            bv[0] = bq.x; bv[1] = bq.y;
#pragma unroll
            for (int x = 0; x < 8; x++) {
                asm("fma.rn.f32x2 %0, %1, %2, %0;" : "+l"(acc[x][0]) : "l"(av[x]), "l"(bv[0]));
                asm("fma.rn.f32x2 %0, %1, %2, %0;" : "+l"(acc[x][1]) : "l"(av[x]), "l"(bv[1]));
            }
        }
        __syncthreads();
    }
#pragma unroll
    for (int x = 0; x < 8; x++) {
        int m = m0 + ty * 8 + x;
#pragma unroll
        for (int y = 0; y < 2; y++) {
            unsigned long long u = acc[x][y];
            float v0 = __uint_as_float((unsigned)u);
            float v1 = __uint_as_float((unsigned)(u >> 32));
            int n = n0 + tx * 4 + y * 2;
            if (bias) { v0 += bias[n]; v1 += bias[n + 1]; }
            if (res)  { v0 += res[(size_t)m * N + n]; v1 += res[(size_t)m * N + n + 1]; }
            C[(size_t)m * N + n]     = v0;
            C[(size_t)m * N + n + 1] = v1;
        }
    }
}

// ---------------------------------------------------------------------------
// 4) Fused softmax + bilinear deformable aggregation (fp16 features).
//    One block per anchor, 256 threads: thread = (sample-parity sp, channel-pair cp).
//    Each thread loads __half2 (2 channels) -> half the LDG issue count.
// ---------------------------------------------------------------------------
__global__ void __launch_bounds__(256) agg_kernel() {
    int a = blockIdx.x;
    int tid = threadIdx.x;
    int lane = tid & 31, warp = tid >> 5;

    __shared__ float  sw[NWTS];        // logits -> softmaxed weights
    __shared__ float2 sp2[NPT * NC];   // p2d
    __shared__ uint4  soff[NSAMP];     // 4 corner offsets (in half2 units)
    __shared__ float4 scw[NSAMP];      // 4 corner bilinear weights
    __shared__ float2 part[256];       // cross-parity reduction

    const float* lrow = g_logits + (size_t)a * NWTS;
    for (int i = tid; i < NWTS; i += 256) sw[i] = lrow[i];
    if (tid < NPT * NC) sp2[tid] = ((const float2*)g_p2d)[(size_t)a * (NPT*NC) + tid];
    __syncthreads();

    // per-group softmax over 312 entries (warp g handles group g)
    {
        int g = warp;
        float m = -1e30f;
        for (int i = lane; i < NSAMP; i += 32) m = fmaxf(m, sw[i * NG + g]);
#pragma unroll
        for (int o = 16; o > 0; o >>= 1) m = fmaxf(m, __shfl_xor_sync(0xffffffffu, m, o));
        float ssum = 0.f;
        for (int i = lane; i < NSAMP; i += 32) {
            float e = expf(sw[i * NG + g] - m);
            sw[i * NG + g] = e;
            ssum += e;
        }
#pragma unroll
        for (int o = 16; o > 0; o >>= 1) ssum += __shfl_xor_sync(0xffffffffu, ssum, o);
        float inv = 1.f / ssum;
        for (int i = lane; i < NSAMP; i += 32) sw[i * NG + g] *= inv;
    }
    __syncthreads();

    // precompute per-sample gather metadata
    for (int s = tid; s < NSAMP; s += 256) {
        int cam = s / (NL * NPT);
        int rr  = s % (NL * NPT);
        int lvl = rr / NPT;
        int pt  = rr % NPT;
        float2 p = sp2[pt * NC + cam];
        int W = c_LW[lvl], H = c_LH[lvl];
        float x = p.x * (float)W - 0.5f;
        float y = p.y * (float)H - 0.5f;
        float xf = floorf(x), yf = floorf(y);
        float wx = x - xf, wy = y - yf;
        int x0 = (int)xf, y0 = (int)yf;
        int x1 = x0 + 1, y1 = y0 + 1;
        bool vx0 = (x0 >= 0) & (x0 < W);
        bool vx1 = (x1 >= 0) & (x1 < W);
        bool vy0 = (y0 >= 0) & (y0 < H);
        bool vy1 = (y1 >= 0) & (y1 < H);
        float w00 = (vx0 && vy0) ? (1.f - wx) * (1.f - wy) : 0.f;
        float w01 = (vx1 && vy0) ? wx * (1.f - wy) : 0.f;
        float w10 = (vx0 && vy1) ? (1.f - wx) * wy : 0.f;
        float w11 = (vx1 && vy1) ? wx * wy : 0.f;
        int x0c = min(max(x0, 0), W - 1), x1c = min(max(x1, 0), W - 1);
        int y0c = min(max(y0, 0), H - 1), y1c = min(max(y1, 0), H - 1);
        unsigned lb = c_LB[lvl];
        unsigned rowb = (unsigned)(cam * H);
        unsigned o00 = (lb + ((rowb + (unsigned)y0c) * (unsigned)W + (unsigned)x0c) * 256u) >> 1;
        unsigned o01 = (lb + ((rowb + (unsigned)y0c) * (unsigned)W + (unsigned)x1c) * 256u) >> 1;
        unsigned o10 = (lb + ((rowb + (unsigned)y1c) * (unsigned)W + (unsigned)x0c) * 256u) >> 1;
        unsigned o11 = (lb + ((rowb + (unsigned)y1c) * (unsigned)W + (unsigned)x1c) * 256u) >> 1;
        soff[s] = make_uint4(o00, o01, o10, o11);
        scw[s]  = make_float4(w00, w01, w10, w11);
    }
    __syncthreads();

    int spar = tid >> 7;            // sample parity (0/1)
    int cp   = tid & 127;           // channel-pair index: channels 2cp, 2cp+1
    int g    = cp >> 4;             // group (both channels in same group)
    float2 acc = make_float2(0.f, 0.f);
    const __half2* __restrict__ F2 = (const __half2*)g_nhwc16;
#pragma unroll 4
    for (int s = spar; s < NSAMP; s += 2) {
        uint4 o  = soff[s];
        float4 c = scw[s];
        float2 f00 = __half22float2(__ldg(F2 + o.x + cp));
        float2 f01 = __half22float2(__ldg(F2 + o.y + cp));
        float2 f10 = __half22float2(__ldg(F2 + o.z + cp));
        float2 f11 = __half22float2(__ldg(F2 + o.w + cp));
        float vx = c.x * f00.x + c.y * f01.x + c.z * f10.x + c.w * f11.x;
        float vy = c.x * f00.y + c.y * f01.y + c.z * f10.y + c.w * f11.y;
        float w = sw[s * NG + g];
        acc.x = fmaf(w, vx, acc.x);
        acc.y = fmaf(w, vy, acc.y);
    }
    part[tid] = acc;
    __syncthreads();
    if (tid < 128) {
        float2 r0 = part[tid], r1 = part[tid + 128];
        float2 r = make_float2(r0.x + r1.x, r0.y + r1.y);
        ((float2*)g_feats)[(size_t)a * 128 + tid] = r;
    }
}

// ---------------------------------------------------------------------------
// launch — inputs bound by unique element counts (order-proof)
// ---------------------------------------------------------------------------
extern "C" void kernel_launch(void* const* d_in, const int* in_sizes, int n_in,
                              void* d_out, int out_size) {
    const float* inst = 0; const float* anchor = 0;
    const float* feat[4] = {0,0,0,0};
    const float* proj = 0; const float* wh = 0;
    const float* Wl = 0; const float* bl = 0;
    const float* Ww = 0; const float* bw = 0;
    const float* Wo = 0; const float* bo = 0;

    for (int i = 0; i < n_in; i++) {
        const float* p = (const float*)d_in[i];
        switch (in_sizes[i]) {
            case 1048576:  inst    = p; break;  // (1,4096,256)
            case 45056:    anchor  = p; break;  // (1,4096,11)
            case 17301504: feat[0] = p; break;
            case 4325376:  feat[1] = p; break;
            case 1081344:  feat[2] = p; break;
            case 270336:   feat[3] = p; break;
            case 96:       proj    = p; break;  // (1,6,4,4)
            case 12:       wh      = p; break;  // (1,6,2)
            case 4608:     Wl      = p; break;  // (256,18)
            case 18:       bl      = p; break;
            case 638976:   Ww      = p; break;  // (256,2496)
            case 2496:     bw      = p; break;
            case 65536:    Wo      = p; break;  // (256,256)
            case 256:      bo      = p; break;
            default: break;                      // pts3d unused
        }
    }
    float* out = (float*)d_out;

    // 1) transposes + fp16 convert
    const int HWs[4] = {64 * 176, 32 * 88, 16 * 44, 8 * 22};
    const unsigned LBs[4] = {0u, 17301504u, 21626880u, 22708224u};
    for (int l = 0; l < 4; l++) {
        dim3 grid((HWs[l] + 31) / 32, ED / 32, NC);
        dim3 block(32, 8);
        transpose_chw_hwc<<<grid, block>>>(feat[l], LBs[l], HWs[l]);
    }

    // 2) per-anchor setup
    setup_kernel<<<NA, 128>>>(inst, anchor, proj, wh, Wl, bl);

    // 3) weight logits GEMM: (4096x256) @ (256x2496) -> g_logits (mode 1)
    {
        dim3 grid(NWTS / 64, NA / 128);
        sgemm_kernel<<<grid, 256>>>(inst, Ww, nullptr, NA, NWTS, ED, bw, nullptr, 1);
    }

    // 4) fused softmax + aggregation
    agg_kernel<<<NA, 256>>>();

    // 5) output GEMM: g_feats (mode 2) @ (256x256) + b_out + inst -> d_out
    {
        dim3 grid(ED / 64, NA / 128);
        sgemm_kernel<<<grid, 256>>>(nullptr, Wo, out, NA, ED, ED, bo, inst, 2);
    }
}

// round 5
// speedup vs baseline: 1.6843x; 1.2403x over previous
#include <cuda_runtime.h>
#include <cuda_fp16.h>
#include <math.h>
#include <stdint.h>

// ---------------------------------------------------------------------------
// Problem constants (fixed by the reference)
// ---------------------------------------------------------------------------
#define NA        4096
#define ED        256      // EMBED_DIMS
#define NG        8        // NUM_GROUPS
#define GD        32       // GROUP_DIMS
#define NL        4        // NUM_LEVELS
#define NC        6        // NUM_CAMS
#define NPT       13       // NUM_PTS (7 fixed + 6 learnable)
#define NSAMP     312      // NC*NL*NPT
#define NWTS      2496     // NSAMP*NG
#define MAXCOR    1280     // >= NSAMP*4

// level dims
__constant__ int   c_LW[4] = {176, 88, 44, 22};
__constant__ int   c_LH[4] = {64, 32, 16, 8};
__constant__ unsigned c_LB[4] = {0u, 17301504u, 21626880u, 22708224u};

__constant__ float c_fix[21] = {
    0.f,0.f,0.f,  0.45f,0.f,0.f,  -0.45f,0.f,0.f,
    0.f,0.45f,0.f, 0.f,-0.45f,0.f, 0.f,0.f,0.45f, 0.f,0.f,-0.45f
};

// ---------------------------------------------------------------------------
// Scratch (static __device__ — device-code references ONLY; host-side address
// of a __device__ symbol is the host shadow and silently "works" via ATS).
// ---------------------------------------------------------------------------
__device__ __half g_nhwc16[22978560];       // all 4 levels, NHWC (cam,h,w,c), fp16
__device__ float  g_logits[NA * NWTS];      // weight logits (softmaxed in agg)
__device__ float  g_p2d[NA * NPT * NC * 2]; // projected points
__device__ float  g_feats[NA * ED];         // aggregated features

// ---------------------------------------------------------------------------
// 1) CHW -> HWC transpose + fp32->fp16 convert (per level).
// ---------------------------------------------------------------------------
__global__ void transpose_chw_hwc(const float* __restrict__ src, unsigned dst_base, int HW) {
    __shared__ float tile[32][33];
    int cam = blockIdx.z;
    int hw0 = blockIdx.x * 32;
    int c0  = blockIdx.y * 32;
    const float* s = src + (size_t)cam * ED * HW;
    __half* d = g_nhwc16 + dst_base + (size_t)cam * HW * ED;
    int tx = threadIdx.x, ty = threadIdx.y;
#pragma unroll
    for (int i = 0; i < 32; i += 8) {
        int c  = c0 + ty + i;
        int hw = hw0 + tx;
        float v = (hw < HW) ? s[(size_t)c * HW + hw] : 0.f;
        tile[ty + i][tx] = v;
    }
    __syncthreads();
#pragma unroll
    for (int i = 0; i < 32; i += 8) {
        int hw = hw0 + ty + i;
        int c  = c0 + tx;
        if (hw < HW) d[(size_t)hw * ED + c] = __float2half(tile[tx][ty + i]);
    }
}

// ---------------------------------------------------------------------------
// 2) Per-anchor setup: learnable points, rotation, projection -> g_p2d
// ---------------------------------------------------------------------------
__global__ void __launch_bounds__(128) setup_kernel(
    const float* __restrict__ inst, const float* __restrict__ anchor,
    const float* __restrict__ proj, const float* __restrict__ wh,
    const float* __restrict__ Wl, const float* __restrict__ bl)
{
    int a = blockIdx.x;
    int tid = threadIdx.x;
    __shared__ float sif[ED];
    __shared__ float sscale[NPT * 3];
    __shared__ float skp[NPT * 3];
    __shared__ float sR[9];
    __shared__ float sts[6];

    const float* f = inst + (size_t)a * ED;
    sif[tid]       = f[tid];
    sif[tid + 128] = f[tid + 128];
    if (tid < 21) sscale[tid] = c_fix[tid];
    __syncthreads();

    const float* an = anchor + (size_t)a * 11;

    if (tid < 18) {
        float acc = bl[tid];
#pragma unroll 8
        for (int i = 0; i < ED; i++) acc = fmaf(sif[i], Wl[i * 18 + tid], acc);
        acc = fminf(fmaxf(acc, -9.21f), 9.21f);
        float sg = 1.f / (1.f + expf(-acc));
        sscale[21 + tid] = sg - 0.5f;
    }
    if (tid == 32) {
        float t0 = an[0], t1 = an[1], t2 = an[2];
        float s0 = an[3], s1 = an[4], s2 = an[5];
        float qw = an[6], qx = an[7], qy = an[8], qz = an[9];
        float inv = rsqrtf(qw*qw + qx*qx + qy*qy + qz*qz);
        qw *= inv; qx *= inv; qy *= inv; qz *= inv;
        float R00 = 1.f - 2.f*(qy*qy + qz*qz), R01 = 2.f*(qx*qy - qw*qz), R02 = 2.f*(qx*qz + qw*qy);
        float R10 = 2.f*(qx*qy + qw*qz), R11 = 1.f - 2.f*(qx*qx + qz*qz), R12 = 2.f*(qy*qz - qw*qx);
        float R20 = 2.f*(qx*qz - qw*qy), R21 = 2.f*(qy*qz + qw*qx), R22 = 1.f - 2.f*(qx*qx + qy*qy);
        sR[0] = R00; sR[1] = R10; sR[2] = R20;
        sR[3] = R01; sR[4] = R11; sR[5] = R21;
        sR[6] = R02; sR[7] = R12; sR[8] = R22;
        sts[0] = t0; sts[1] = t1; sts[2] = t2;
        sts[3] = s0; sts[4] = s1; sts[5] = s2;
    }
    __syncthreads();
    if (tid < NPT) {
        float v0 = sscale[tid*3+0] * sts[3];
        float v1 = sscale[tid*3+1] * sts[4];
        float v2 = sscale[tid*3+2] * sts[5];
        skp[tid*3+0] = sR[0]*v0 + sR[1]*v1 + sR[2]*v2 + sts[0];
        skp[tid*3+1] = sR[3]*v0 + sR[4]*v1 + sR[5]*v2 + sts[1];
        skp[tid*3+2] = sR[6]*v0 + sR[7]*v1 + sR[8]*v2 + sts[2];
    }
    __syncthreads();
    if (tid < NPT * NC) {
        int pt = tid / NC, cam = tid % NC;
        float x = skp[pt*3+0], y = skp[pt*3+1], z = skp[pt*3+2];
        const float* P = proj + cam * 16;
        float px = P[0]*x + P[1]*y + P[2]*z  + P[3];
        float py = P[4]*x + P[5]*y + P[6]*z  + P[7];
        float pz = P[8]*x + P[9]*y + P[10]*z + P[11];
        pz = fmaxf(pz, 1e-5f);
        float u = (px / pz) / wh[cam*2+0];
        float v = (py / pz) / wh[cam*2+1];
        u = fminf(fmaxf(u, 0.f), 0.9999f);
        v = fminf(fmaxf(v, 0.f), 0.9999f);
        g_p2d[((size_t)a * (NPT*NC) + tid) * 2 + 0] = u;
        g_p2d[((size_t)a * (NPT*NC) + tid) * 2 + 1] = v;
    }
}

// ---------------------------------------------------------------------------
// 3/5) Tiled SGEMM using packed fma.rn.f32x2 (2x FFMA throughput).
//      mode 1: C := g_logits   mode 2: A := g_feats   (device-side symbols)
// ---------------------------------------------------------------------------
__global__ void __launch_bounds__(256) sgemm_kernel(
    const float* __restrict__ A, const float* __restrict__ B, float* __restrict__ C,
    int M, int N, int K, const float* __restrict__ bias, const float* __restrict__ res,
    int mode)
{
    if (mode == 1) C = g_logits;
    if (mode == 2) A = g_feats;

    const int BM = 128, BN = 64, BK = 16;
    __shared__ float2 Asd[BK][BM + 2];
    __shared__ float  Bs[BK][BN];
    int tid = threadIdx.x;
    int tx = tid & 15, ty = tid >> 4;
    int m0 = blockIdx.y * BM, n0 = blockIdx.x * BN;

    unsigned long long acc[8][2];
#pragma unroll
    for (int x = 0; x < 8; x++) { acc[x][0] = 0ull; acc[x][1] = 0ull; }

    for (int k0 = 0; k0 < K; k0 += BK) {
#pragma unroll
        for (int i = 0; i < 8; i++) {
            int e = tid + i * 256;
            int m = e >> 4, kk = e & 15;
            float v = A[(size_t)(m0 + m) * K + k0 + kk];
            Asd[kk][m] = make_float2(v, v);
        }
#pragma unroll
        for (int i = 0; i < 4; i++) {
            int e = tid + i * 256;
            int kk = e >> 6, n = e & 63;
            Bs[kk][n] = B[(size_t)(k0 + kk) * N + n0 + n];
        }
        __syncthreads();
#pragma unroll
        for (int kk = 0; kk < BK; kk++) {
            unsigned long long av[8], bv[2];
            const ulonglong2* ap = (const ulonglong2*)&Asd[kk][ty * 8];
            ulonglong2 t;
            t = ap[0]; av[0] = t.x; av[1] = t.y;
            t = ap[1]; av[2] = t.x; av[3] = t.y;
            t = ap[2]; av[4] = t.x; av[5] = t.y;
            t = ap[3]; av[6] = t.x; av[7] = t.y;
            ulonglong2 bq = *(const ulonglong2*)&Bs[kk][tx * 4];
            bv[0] = bq.x; bv[1] = bq.y;
#pragma unroll
            for (int x = 0; x < 8; x++) {
                asm("fma.rn.f32x2 %0, %1, %2, %0;" : "+l"(acc[x][0]) : "l"(av[x]), "l"(bv[0]));
                asm("fma.rn.f32x2 %0, %1, %2, %0;" : "+l"(acc[x][1]) : "l"(av[x]), "l"(bv[1]));
            }
        }
        __syncthreads();
    }
#pragma unroll
    for (int x = 0; x < 8; x++) {
        int m = m0 + ty * 8 + x;
#pragma unroll
        for (int y = 0; y < 2; y++) {
            unsigned long long u = acc[x][y];
            float v0 = __uint_as_float((unsigned)u);
            float v1 = __uint_as_float((unsigned)(u >> 32));
            int n = n0 + tx * 4 + y * 2;
            if (bias) { v0 += bias[n]; v1 += bias[n + 1]; }
            if (res)  { v0 += res[(size_t)m * N + n]; v1 += res[(size_t)m * N + n + 1]; }
            C[(size_t)m * N + n]     = v0;
            C[(size_t)m * N + n + 1] = v1;
        }
    }
}

// ---------------------------------------------------------------------------
// per-sample bilinear corner metadata (shared by count & fill passes;
// identical float ops -> identical counts, deterministic)
// ---------------------------------------------------------------------------
struct Corners {
    unsigned o[4];   // half2-unit offsets
    float    w[4];   // bilinear weights (0 if invalid)
};

__device__ __forceinline__ Corners corner_meta(float2 p, int s) {
    int cam = s / (NL * NPT);
    int rr  = s % (NL * NPT);
    int lvl = rr / NPT;
    Corners r;
    int W = c_LW[lvl], H = c_LH[lvl];
    float x = p.x * (float)W - 0.5f;
    float y = p.y * (float)H - 0.5f;
    float xf = floorf(x), yf = floorf(y);
    float wx = x - xf, wy = y - yf;
    int x0 = (int)xf, y0 = (int)yf;
    int x1 = x0 + 1, y1 = y0 + 1;
    bool vx0 = (x0 >= 0) & (x0 < W);
    bool vx1 = (x1 >= 0) & (x1 < W);
    bool vy0 = (y0 >= 0) & (y0 < H);
    bool vy1 = (y1 >= 0) & (y1 < H);
    r.w[0] = (vx0 && vy0) ? (1.f - wx) * (1.f - wy) : 0.f;
    r.w[1] = (vx1 && vy0) ? wx * (1.f - wy) : 0.f;
    r.w[2] = (vx0 && vy1) ? (1.f - wx) * wy : 0.f;
    r.w[3] = (vx1 && vy1) ? wx * wy : 0.f;
    int x0c = min(max(x0, 0), W - 1), x1c = min(max(x1, 0), W - 1);
    int y0c = min(max(y0, 0), H - 1), y1c = min(max(y1, 0), H - 1);
    unsigned lb = c_LB[lvl];
    unsigned rowb = (unsigned)(cam * H);
    r.o[0] = (lb + ((rowb + (unsigned)y0c) * (unsigned)W + (unsigned)x0c) * 256u) >> 1;
    r.o[1] = (lb + ((rowb + (unsigned)y0c) * (unsigned)W + (unsigned)x1c) * 256u) >> 1;
    r.o[2] = (lb + ((rowb + (unsigned)y1c) * (unsigned)W + (unsigned)x0c) * 256u) >> 1;
    r.o[3] = (lb + ((rowb + (unsigned)y1c) * (unsigned)W + (unsigned)x1c) * 256u) >> 1;
    return r;
}

// ---------------------------------------------------------------------------
// 4) Fused softmax + compacted bilinear aggregation (fp16 features).
//    One block per anchor, 256 threads = 2 entry-parities x 128 channel-pairs.
//    Zero-weight corners (border-clamped samples) are compacted away exactly.
// ---------------------------------------------------------------------------
__global__ void __launch_bounds__(256) agg_kernel() {
    int a = blockIdx.x;
    int tid = threadIdx.x;
    int lane = tid & 31, warp = tid >> 5;

    __shared__ float  sw[NWTS];          // softmaxed weights
    __shared__ float2 sp2[NPT * NC];     // p2d
    __shared__ unsigned fo[MAXCOR];      // compacted corner offsets (half2 units)
    __shared__ float2   fm[MAXCOR];      // (corner weight, bitcast widx = s*NG)
    __shared__ int scnt[320];            // per-sample corner counts
    __shared__ int sbase[NSAMP];         // exclusive prefix
    __shared__ int sT;                   // total corners
    __shared__ float2 part[256];

    const float* lrow = g_logits + (size_t)a * NWTS;
    for (int i = tid; i < NWTS; i += 256) sw[i] = lrow[i];
    if (tid < NPT * NC) sp2[tid] = ((const float2*)g_p2d)[(size_t)a * (NPT*NC) + tid];
    if (tid >= NSAMP && tid < 320) scnt[tid] = 0;
    __syncthreads();

    // per-group softmax over 312 entries (warp g handles group g)
    {
        int g = warp;
        float m = -1e30f;
        for (int i = lane; i < NSAMP; i += 32) m = fmaxf(m, sw[i * NG + g]);
#pragma unroll
        for (int o = 16; o > 0; o >>= 1) m = fmaxf(m, __shfl_xor_sync(0xffffffffu, m, o));
        float ssum = 0.f;
        for (int i = lane; i < NSAMP; i += 32) {
            float e = expf(sw[i * NG + g] - m);
            sw[i * NG + g] = e;
            ssum += e;
        }
#pragma unroll
        for (int o = 16; o > 0; o >>= 1) ssum += __shfl_xor_sync(0xffffffffu, ssum, o);
        float inv = 1.f / ssum;
        for (int i = lane; i < NSAMP; i += 32) sw[i * NG + g] *= inv;
    }

    // pass 1: per-sample valid-corner counts
    for (int s = tid; s < NSAMP; s += 256) {
        int pt = (s % (NL * NPT)) % NPT, cam = s / (NL * NPT);
        Corners cr = corner_meta(sp2[pt * NC + cam], s);
        scnt[s] = (cr.w[0] != 0.f) + (cr.w[1] != 0.f) + (cr.w[2] != 0.f) + (cr.w[3] != 0.f);
    }
    __syncthreads();

    // deterministic exclusive scan over 312 counts (warp 0, 10 samples/lane)
    if (tid < 32) {
        int l = tid;
        int tot = 0;
#pragma unroll
        for (int k = 0; k < 10; k++) {
            int s = l * 10 + k;
            tot += (s < NSAMP) ? scnt[s] : 0;
        }
        int inc = tot;
#pragma unroll
        for (int o = 1; o < 32; o <<= 1) {
            int v = __shfl_up_sync(0xffffffffu, inc, o);
            if (l >= o) inc += v;
        }
        int run = inc - tot;
#pragma unroll
        for (int k = 0; k < 10; k++) {
            int s = l * 10 + k;
            if (s < NSAMP) { sbase[s] = run; run += scnt[s]; }
        }
        if (l == 31) sT = run;
    }
    __syncthreads();

    // pass 2: fill compacted corner list
    for (int s = tid; s < NSAMP; s += 256) {
        int pt = (s % (NL * NPT)) % NPT, cam = s / (NL * NPT);
        Corners cr = corner_meta(sp2[pt * NC + cam], s);
        int b = sbase[s];
        float widx = __int_as_float(s * NG);
#pragma unroll
        for (int k = 0; k < 4; k++) {
            if (cr.w[k] != 0.f) {
                fo[b] = cr.o[k];
                fm[b] = make_float2(cr.w[k], widx);
                b++;
            }
        }
    }
    __syncthreads();

    const int T = sT;
    int spar = tid >> 7;            // entry parity (0/1)
    int cp   = tid & 127;           // channel-pair index: channels 2cp, 2cp+1
    int g    = cp >> 4;             // group
    float2 acc = make_float2(0.f, 0.f);
    const __half2* __restrict__ F2 = (const __half2*)g_nhwc16;
#pragma unroll 4
    for (int j = spar; j < T; j += 2) {
        unsigned o = fo[j];
        float2 m = fm[j];
        float w = sw[__float_as_int(m.y) + g] * m.x;
        float2 f = __half22float2(__ldg(F2 + o + cp));
        acc.x = fmaf(w, f.x, acc.x);
        acc.y = fmaf(w, f.y, acc.y);
    }
    part[tid] = acc;
    __syncthreads();
    if (tid < 128) {
        float2 r0 = part[tid], r1 = part[tid + 128];
        float2 r = make_float2(r0.x + r1.x, r0.y + r1.y);
        ((float2*)g_feats)[(size_t)a * 128 + tid] = r;
    }
}

// ---------------------------------------------------------------------------
// launch — inputs bound by unique element counts (order-proof)
// ---------------------------------------------------------------------------
extern "C" void kernel_launch(void* const* d_in, const int* in_sizes, int n_in,
                              void* d_out, int out_size) {
    const float* inst = 0; const float* anchor = 0;
    const float* feat[4] = {0,0,0,0};
    const float* proj = 0; const float* wh = 0;
    const float* Wl = 0; const float* bl = 0;
    const float* Ww = 0; const float* bw = 0;
    const float* Wo = 0; const float* bo = 0;

    for (int i = 0; i < n_in; i++) {
        const float* p = (const float*)d_in[i];
        switch (in_sizes[i]) {
            case 1048576:  inst    = p; break;  // (1,4096,256)
            case 45056:    anchor  = p; break;  // (1,4096,11)
            case 17301504: feat[0] = p; break;
            case 4325376:  feat[1] = p; break;
            case 1081344:  feat[2] = p; break;
            case 270336:   feat[3] = p; break;
            case 96:       proj    = p; break;  // (1,6,4,4)
            case 12:       wh      = p; break;  // (1,6,2)
            case 4608:     Wl      = p; break;  // (256,18)
            case 18:       bl      = p; break;
            case 638976:   Ww      = p; break;  // (256,2496)
            case 2496:     bw      = p; break;
            case 65536:    Wo      = p; break;  // (256,256)
            case 256:      bo      = p; break;
            default: break;                      // pts3d unused
        }
    }
    float* out = (float*)d_out;

    // 1) transposes + fp16 convert
    const int HWs[4] = {64 * 176, 32 * 88, 16 * 44, 8 * 22};
    const unsigned LBs[4] = {0u, 17301504u, 21626880u, 22708224u};
    for (int l = 0; l < 4; l++) {
        dim3 grid((HWs[l] + 31) / 32, ED / 32, NC);
        dim3 block(32, 8);
        transpose_chw_hwc<<<grid, block>>>(feat[l], LBs[l], HWs[l]);
    }

    // 2) per-anchor setup
    setup_kernel<<<NA, 128>>>(inst, anchor, proj, wh, Wl, bl);

    // 3) weight logits GEMM: (4096x256) @ (256x2496) -> g_logits (mode 1)
    {
        dim3 grid(NWTS / 64, NA / 128);
        sgemm_kernel<<<grid, 256>>>(inst, Ww, nullptr, NA, NWTS, ED, bw, nullptr, 1);
    }

    // 4) fused softmax + compacted aggregation
    agg_kernel<<<NA, 256>>>();

    // 5) output GEMM: g_feats (mode 2) @ (256x256) + b_out + inst -> d_out
    {
        dim3 grid(ED / 64, NA / 128);
        sgemm_kernel<<<grid, 256>>>(nullptr, Wo, out, NA, ED, ED, bo, inst, 2);
    }
}

// round 7
// speedup vs baseline: 1.9145x; 1.1367x over previous
#include <cuda_runtime.h>
#include <cuda_fp16.h>
#include <cuda_fp8.h>
#include <math.h>
#include <stdint.h>

// ---------------------------------------------------------------------------
// Problem constants (fixed by the reference)
// ---------------------------------------------------------------------------
#define NA        4096
#define ED        256      // EMBED_DIMS
#define NG        8        // NUM_GROUPS
#define GD        32       // GROUP_DIMS
#define NL        4        // NUM_LEVELS
#define NC        6        // NUM_CAMS
#define NPT       13       // NUM_PTS (7 fixed + 6 learnable)
#define NSAMP     312      // NC*NL*NPT
#define NWTS      2496     // NSAMP*NG
#define MAXCOR    1280     // >= NSAMP*4

// level dims
__constant__ int   c_LW[4] = {176, 88, 44, 22};
__constant__ int   c_LH[4] = {64, 32, 16, 8};
__constant__ unsigned c_LB[4] = {0u, 17301504u, 21626880u, 22708224u};  // byte offsets (1B/elem)

__constant__ float c_fix[21] = {
    0.f,0.f,0.f,  0.45f,0.f,0.f,  -0.45f,0.f,0.f,
    0.f,0.45f,0.f, 0.f,-0.45f,0.f, 0.f,0.f,0.45f, 0.f,0.f,-0.45f
};

// ---------------------------------------------------------------------------
// Scratch (static __device__ — device-code references ONLY; host-side address
// of a __device__ symbol is the host shadow and silently "works" via ATS).
// g_f8 MUST be 16B-aligned: it is accessed through uint2* (8B vector loads).
// ---------------------------------------------------------------------------
__device__ __align__(16) unsigned char g_f8[22978560]; // 4 levels, NHWC, fp8 e4m3
__device__ float  g_logits[NA * NWTS];      // weight logits (softmaxed in agg)
__device__ float  g_p2d[NA * NPT * NC * 2]; // projected points
__device__ float  g_feats[NA * ED];         // aggregated features

// ---------------------------------------------------------------------------
// 1) CHW -> HWC transpose + fp32->fp8(e4m3) convert (per level).
//    Warp writes 32 consecutive bytes = one full 32B sector -> no write waste.
// ---------------------------------------------------------------------------
__global__ void transpose_chw_hwc(const float* __restrict__ src, unsigned dst_base, int HW) {
    __shared__ float tile[32][33];
    int cam = blockIdx.z;
    int hw0 = blockIdx.x * 32;
    int c0  = blockIdx.y * 32;
    const float* s = src + (size_t)cam * ED * HW;
    unsigned char* d = g_f8 + dst_base + (size_t)cam * HW * ED;
    int tx = threadIdx.x, ty = threadIdx.y;
#pragma unroll
    for (int i = 0; i < 32; i += 8) {
        int c  = c0 + ty + i;
        int hw = hw0 + tx;
        float v = (hw < HW) ? s[(size_t)c * HW + hw] : 0.f;
        tile[ty + i][tx] = v;
    }
    __syncthreads();
#pragma unroll
    for (int i = 0; i < 32; i += 8) {
        int hw = hw0 + ty + i;
        int c  = c0 + tx;
        if (hw < HW)
            d[(size_t)hw * ED + c] =
                (unsigned char)__nv_cvt_float_to_fp8(tile[tx][ty + i], __NV_SATFINITE, __NV_E4M3);
    }
}

// ---------------------------------------------------------------------------
// 2) Per-anchor setup: learnable points, rotation, projection -> g_p2d
// ---------------------------------------------------------------------------
__global__ void __launch_bounds__(128) setup_kernel(
    const float* __restrict__ inst, const float* __restrict__ anchor,
    const float* __restrict__ proj, const float* __restrict__ wh,
    const float* __restrict__ Wl, const float* __restrict__ bl)
{
    int a = blockIdx.x;
    int tid = threadIdx.x;
    __shared__ float sif[ED];
    __shared__ float sscale[NPT * 3];
    __shared__ float skp[NPT * 3];
    __shared__ float sR[9];
    __shared__ float sts[6];

    const float* f = inst + (size_t)a * ED;
    sif[tid]       = f[tid];
    sif[tid + 128] = f[tid + 128];
    if (tid < 21) sscale[tid] = c_fix[tid];
    __syncthreads();

    const float* an = anchor + (size_t)a * 11;

    if (tid < 18) {
        float acc = bl[tid];
#pragma unroll 8
        for (int i = 0; i < ED; i++) acc = fmaf(sif[i], Wl[i * 18 + tid], acc);
        acc = fminf(fmaxf(acc, -9.21f), 9.21f);
        float sg = 1.f / (1.f + expf(-acc));
        sscale[21 + tid] = sg - 0.5f;
    }
    if (tid == 32) {
        float t0 = an[0], t1 = an[1], t2 = an[2];
        float s0 = an[3], s1 = an[4], s2 = an[5];
        float qw = an[6], qx = an[7], qy = an[8], qz = an[9];
        float inv = rsqrtf(qw*qw + qx*qx + qy*qy + qz*qz);
        qw *= inv; qx *= inv; qy *= inv; qz *= inv;
        float R00 = 1.f - 2.f*(qy*qy + qz*qz), R01 = 2.f*(qx*qy - qw*qz), R02 = 2.f*(qx*qz + qw*qy);
        float R10 = 2.f*(qx*qy + qw*qz), R11 = 1.f - 2.f*(qx*qx + qz*qz), R12 = 2.f*(qy*qz - qw*qx);
        float R20 = 2.f*(qx*qz - qw*qy), R21 = 2.f*(qy*qz + qw*qx), R22 = 1.f - 2.f*(qx*qx + qy*qy);
        sR[0] = R00; sR[1] = R10; sR[2] = R20;
        sR[3] = R01; sR[4] = R11; sR[5] = R21;
        sR[6] = R02; sR[7] = R12; sR[8] = R22;
        sts[0] = t0; sts[1] = t1; sts[2] = t2;
        sts[3] = s0; sts[4] = s1; sts[5] = s2;
    }
    __syncthreads();
    if (tid < NPT) {
        float v0 = sscale[tid*3+0] * sts[3];
        float v1 = sscale[tid*3+1] * sts[4];
        float v2 = sscale[tid*3+2] * sts[5];
        skp[tid*3+0] = sR[0]*v0 + sR[1]*v1 + sR[2]*v2 + sts[0];
        skp[tid*3+1] = sR[3]*v0 + sR[4]*v1 + sR[5]*v2 + sts[1];
        skp[tid*3+2] = sR[6]*v0 + sR[7]*v1 + sR[8]*v2 + sts[2];
    }
    __syncthreads();
    if (tid < NPT * NC) {
        int pt = tid / NC, cam = tid % NC;
        float x = skp[pt*3+0], y = skp[pt*3+1], z = skp[pt*3+2];
        const float* P = proj + cam * 16;
        float px = P[0]*x + P[1]*y + P[2]*z  + P[3];
        float py = P[4]*x + P[5]*y + P[6]*z  + P[7];
        float pz = P[8]*x + P[9]*y + P[10]*z + P[11];
        pz = fmaxf(pz, 1e-5f);
        float u = (px / pz) / wh[cam*2+0];
        float v = (py / pz) / wh[cam*2+1];
        u = fminf(fmaxf(u, 0.f), 0.9999f);
        v = fminf(fmaxf(v, 0.f), 0.9999f);
        g_p2d[((size_t)a * (NPT*NC) + tid) * 2 + 0] = u;
        g_p2d[((size_t)a * (NPT*NC) + tid) * 2 + 1] = v;
    }
}

// ---------------------------------------------------------------------------
// 3/5) Tiled SGEMM using packed fma.rn.f32x2 (2x FFMA throughput).
//      mode 1: C := g_logits   mode 2: A := g_feats   (device-side symbols)
// ---------------------------------------------------------------------------
__global__ void __launch_bounds__(256) sgemm_kernel(
    const float* __restrict__ A, const float* __restrict__ B, float* __restrict__ C,
    int M, int N, int K, const float* __restrict__ bias, const float* __restrict__ res,
    int mode)
{
    if (mode == 1) C = g_logits;
    if (mode == 2) A = g_feats;

    const int BM = 128, BN = 64, BK = 16;
    __shared__ float2 Asd[BK][BM + 2];
    __shared__ float  Bs[BK][BN];
    int tid = threadIdx.x;
    int tx = tid & 15, ty = tid >> 4;
    int m0 = blockIdx.y * BM, n0 = blockIdx.x * BN;

    unsigned long long acc[8][2];
#pragma unroll
    for (int x = 0; x < 8; x++) { acc[x][0] = 0ull; acc[x][1] = 0ull; }

    for (int k0 = 0; k0 < K; k0 += BK) {
#pragma unroll
        for (int i = 0; i < 8; i++) {
            int e = tid + i * 256;
            int m = e >> 4, kk = e & 15;
            float v = A[(size_t)(m0 + m) * K + k0 + kk];
            Asd[kk][m] = make_float2(v, v);
        }
#pragma unroll
        for (int i = 0; i < 4; i++) {
            int e = tid + i * 256;
            int kk = e >> 6, n = e & 63;
            Bs[kk][n] = B[(size_t)(k0 + kk) * N + n0 + n];
        }
        __syncthreads();
#pragma unroll
        for (int kk = 0; kk < BK; kk++) {
            unsigned long long av[8], bv[2];
            const ulonglong2* ap = (const ulonglong2*)&Asd[kk][ty * 8];
            ulonglong2 t;
            t = ap[0]; av[0] = t.x; av[1] = t.y;
            t = ap[1]; av[2] = t.x; av[3] = t.y;
            t = ap[2]; av[4] = t.x; av[5] = t.y;
            t = ap[3]; av[6] = t.x; av[7] = t.y;
            ulonglong2 bq = *(const ulonglong2*)&Bs[kk][tx * 4];
            bv[0] = bq.x; bv[1] = bq.y;
#pragma unroll
            for (int x = 0; x < 8; x++) {
                asm("fma.rn.f32x2 %0, %1, %2, %0;" : "+l"(acc[x][0]) : "l"(av[x]), "l"(bv[0]));
                asm("fma.rn.f32x2 %0, %1, %2, %0;" : "+l"(acc[x][1]) : "l"(av[x]), "l"(bv[1]));
            }
        }
        __syncthreads();
    }
#pragma unroll
    for (int x = 0; x < 8; x++) {
        int m = m0 + ty * 8 + x;
#pragma unroll
        for (int y = 0; y < 2; y++) {
            unsigned long long u = acc[x][y];
            float v0 = __uint_as_float((unsigned)u);
            float v1 = __uint_as_float((unsigned)(u >> 32));
            int n = n0 + tx * 4 + y * 2;
            if (bias) { v0 += bias[n]; v1 += bias[n + 1]; }
            if (res)  { v0 += res[(size_t)m * N + n]; v1 += res[(size_t)m * N + n + 1]; }
            C[(size_t)m * N + n]     = v0;
            C[(size_t)m * N + n + 1] = v1;
        }
    }
}

// ---------------------------------------------------------------------------
// per-sample bilinear corner metadata (shared by count & fill passes)
// ---------------------------------------------------------------------------
struct Corners {
    unsigned o[4];   // uint2-unit offsets (8 fp8 bytes per unit)
    float    w[4];   // bilinear weights (0 if invalid)
};

__device__ __forceinline__ Corners corner_meta(float2 p, int s) {
    int cam = s / (NL * NPT);
    int rr  = s % (NL * NPT);
    int lvl = rr / NPT;
    Corners r;
    int W = c_LW[lvl], H = c_LH[lvl];
    float x = p.x * (float)W - 0.5f;
    float y = p.y * (float)H - 0.5f;
    float xf = floorf(x), yf = floorf(y);
    float wx = x - xf, wy = y - yf;
    int x0 = (int)xf, y0 = (int)yf;
    int x1 = x0 + 1, y1 = y0 + 1;
    bool vx0 = (x0 >= 0) & (x0 < W);
    bool vx1 = (x1 >= 0) & (x1 < W);
    bool vy0 = (y0 >= 0) & (y0 < H);
    bool vy1 = (y1 >= 0) & (y1 < H);
    r.w[0] = (vx0 && vy0) ? (1.f - wx) * (1.f - wy) : 0.f;
    r.w[1] = (vx1 && vy0) ? wx * (1.f - wy) : 0.f;
    r.w[2] = (vx0 && vy1) ? (1.f - wx) * wy : 0.f;
    r.w[3] = (vx1 && vy1) ? wx * wy : 0.f;
    int x0c = min(max(x0, 0), W - 1), x1c = min(max(x1, 0), W - 1);
    int y0c = min(max(y0, 0), H - 1), y1c = min(max(y1, 0), H - 1);
    unsigned lb = c_LB[lvl];
    unsigned rowb = (unsigned)(cam * H);
    // byte offset = lb + texel*256; uint2 units = >>3
    r.o[0] = (lb + ((rowb + (unsigned)y0c) * (unsigned)W + (unsigned)x0c) * 256u) >> 3;
    r.o[1] = (lb + ((rowb + (unsigned)y0c) * (unsigned)W + (unsigned)x1c) * 256u) >> 3;
    r.o[2] = (lb + ((rowb + (unsigned)y1c) * (unsigned)W + (unsigned)x0c) * 256u) >> 3;
    r.o[3] = (lb + ((rowb + (unsigned)y1c) * (unsigned)W + (unsigned)x1c) * 256u) >> 3;
    return r;
}

// decode 4 packed e4m3 -> float4
__device__ __forceinline__ float4 fp8x4_to_float4(unsigned v) {
    __half2_raw h01 = __nv_cvt_fp8x2_to_halfraw2((__nv_fp8x2_storage_t)(v & 0xffffu), __NV_E4M3);
    __half2_raw h23 = __nv_cvt_fp8x2_to_halfraw2((__nv_fp8x2_storage_t)(v >> 16), __NV_E4M3);
    float2 a = __half22float2(*reinterpret_cast<__half2*>(&h01));
    float2 b = __half22float2(*reinterpret_cast<__half2*>(&h23));
    return make_float4(a.x, a.y, b.x, b.y);
}

// ---------------------------------------------------------------------------
// 4) Fused softmax + compacted bilinear aggregation (fp8 features).
//    One block per anchor; 8 warps = 8 corner-parities; lane = 8-channel slab.
//    Each warp loads one full 256B corner per iteration (perfectly coalesced).
// ---------------------------------------------------------------------------
__global__ void __launch_bounds__(256) agg_kernel() {
    int a = blockIdx.x;
    int tid = threadIdx.x;
    int lane = tid & 31, warp = tid >> 5;

    __shared__ float  sw[NWTS];          // softmaxed weights
    __shared__ float2 sp2[NPT * NC];     // p2d
    __shared__ unsigned fo[MAXCOR];      // compacted corner offsets (uint2 units)
    __shared__ float2   fm[MAXCOR];      // (corner weight, bitcast widx = s*NG)
    __shared__ int scnt[320];            // per-sample corner counts
    __shared__ int sbase[NSAMP];         // exclusive prefix
    __shared__ int sT;                   // total corners
    __shared__ __align__(16) float spart[8 * ED];  // per-parity partial sums (float4-accessed)

    const float* lrow = g_logits + (size_t)a * NWTS;
    for (int i = tid; i < NWTS; i += 256) sw[i] = lrow[i];
    if (tid < NPT * NC) sp2[tid] = ((const float2*)g_p2d)[(size_t)a * (NPT*NC) + tid];
    if (tid >= NSAMP && tid < 320) scnt[tid] = 0;
    __syncthreads();

    // per-group softmax over 312 entries (warp g handles group g)
    {
        int g = warp;
        float m = -1e30f;
        for (int i = lane; i < NSAMP; i += 32) m = fmaxf(m, sw[i * NG + g]);
#pragma unroll
        for (int o = 16; o > 0; o >>= 1) m = fmaxf(m, __shfl_xor_sync(0xffffffffu, m, o));
        float ssum = 0.f;
        for (int i = lane; i < NSAMP; i += 32) {
            float e = expf(sw[i * NG + g] - m);
            sw[i * NG + g] = e;
            ssum += e;
        }
#pragma unroll
        for (int o = 16; o > 0; o >>= 1) ssum += __shfl_xor_sync(0xffffffffu, ssum, o);
        float inv = 1.f / ssum;
        for (int i = lane; i < NSAMP; i += 32) sw[i * NG + g] *= inv;
    }

    // pass 1: per-sample valid-corner counts
    for (int s = tid; s < NSAMP; s += 256) {
        int pt = (s % (NL * NPT)) % NPT, cam = s / (NL * NPT);
        Corners cr = corner_meta(sp2[pt * NC + cam], s);
        scnt[s] = (cr.w[0] != 0.f) + (cr.w[1] != 0.f) + (cr.w[2] != 0.f) + (cr.w[3] != 0.f);
    }
    __syncthreads();

    // deterministic exclusive scan over 312 counts (warp 0, 10 samples/lane)
    if (tid < 32) {
        int l = tid;
        int tot = 0;
#pragma unroll
        for (int k = 0; k < 10; k++) {
            int s = l * 10 + k;
            tot += (s < NSAMP) ? scnt[s] : 0;
        }
        int inc = tot;
#pragma unroll
        for (int o = 1; o < 32; o <<= 1) {
            int v = __shfl_up_sync(0xffffffffu, inc, o);
            if (l >= o) inc += v;
        }
        int run = inc - tot;
#pragma unroll
        for (int k = 0; k < 10; k++) {
            int s = l * 10 + k;
            if (s < NSAMP) { sbase[s] = run; run += scnt[s]; }
        }
        if (l == 31) sT = run;
    }
    __syncthreads();

    // pass 2: fill compacted corner list
    for (int s = tid; s < NSAMP; s += 256) {
        int pt = (s % (NL * NPT)) % NPT, cam = s / (NL * NPT);
        Corners cr = corner_meta(sp2[pt * NC + cam], s);
        int b = sbase[s];
        float widx = __int_as_float(s * NG);
#pragma unroll
        for (int k = 0; k < 4; k++) {
            if (cr.w[k] != 0.f) {
                fo[b] = cr.o[k];
                fm[b] = make_float2(cr.w[k], widx);
                b++;
            }
        }
    }
    __syncthreads();

    const int T = sT;
    int g = lane >> 2;                  // group of this 8-channel slab (32 ch/group)
    float acc0 = 0.f, acc1 = 0.f, acc2 = 0.f, acc3 = 0.f;
    float acc4 = 0.f, acc5 = 0.f, acc6 = 0.f, acc7 = 0.f;
    const uint2* __restrict__ F8 = (const uint2*)g_f8;
#pragma unroll 4
    for (int j = warp; j < T; j += 8) {
        unsigned o = fo[j];
        float2 m = fm[j];
        float w = sw[__float_as_int(m.y) + g] * m.x;
        uint2 u = __ldg(F8 + o + lane);
        float4 fa = fp8x4_to_float4(u.x);
        float4 fb = fp8x4_to_float4(u.y);
        acc0 = fmaf(w, fa.x, acc0);
        acc1 = fmaf(w, fa.y, acc1);
        acc2 = fmaf(w, fa.z, acc2);
        acc3 = fmaf(w, fa.w, acc3);
        acc4 = fmaf(w, fb.x, acc4);
        acc5 = fmaf(w, fb.y, acc5);
        acc6 = fmaf(w, fb.z, acc6);
        acc7 = fmaf(w, fb.w, acc7);
    }
    // spart[parity][channel]; channel = lane*8 + k
    {
        float4* sp4 = (float4*)&spart[warp * ED + lane * 8];
        sp4[0] = make_float4(acc0, acc1, acc2, acc3);
        sp4[1] = make_float4(acc4, acc5, acc6, acc7);
    }
    __syncthreads();
    // reduce 8 parities per channel
    {
        int ch = tid;
        float r = spart[ch];
#pragma unroll
        for (int p = 1; p < 8; p++) r += spart[p * ED + ch];
        g_feats[(size_t)a * ED + ch] = r;
    }
}

// ---------------------------------------------------------------------------
// launch — inputs bound by unique element counts (order-proof)
// ---------------------------------------------------------------------------
extern "C" void kernel_launch(void* const* d_in, const int* in_sizes, int n_in,
                              void* d_out, int out_size) {
    const float* inst = 0; const float* anchor = 0;
    const float* feat[4] = {0,0,0,0};
    const float* proj = 0; const float* wh = 0;
    const float* Wl = 0; const float* bl = 0;
    const float* Ww = 0; const float* bw = 0;
    const float* Wo = 0; const float* bo = 0;

    for (int i = 0; i < n_in; i++) {
        const float* p = (const float*)d_in[i];
        switch (in_sizes[i]) {
            case 1048576:  inst    = p; break;  // (1,4096,256)
            case 45056:    anchor  = p; break;  // (1,4096,11)
            case 17301504: feat[0] = p; break;
            case 4325376:  feat[1] = p; break;
            case 1081344:  feat[2] = p; break;
            case 270336:   feat[3] = p; break;
            case 96:       proj    = p; break;  // (1,6,4,4)
            case 12:       wh      = p; break;  // (1,6,2)
            case 4608:     Wl      = p; break;  // (256,18)
            case 18:       bl      = p; break;
            case 638976:   Ww      = p; break;  // (256,2496)
            case 2496:     bw      = p; break;
            case 65536:    Wo      = p; break;  // (256,256)
            case 256:      bo      = p; break;
            default: break;                      // pts3d unused
        }
    }
    float* out = (float*)d_out;

    // 1) transposes + fp8 convert
    const int HWs[4] = {64 * 176, 32 * 88, 16 * 44, 8 * 22};
    const unsigned LBs[4] = {0u, 17301504u, 21626880u, 22708224u};
    for (int l = 0; l < 4; l++) {
        dim3 grid((HWs[l] + 31) / 32, ED / 32, NC);
        dim3 block(32, 8);
        transpose_chw_hwc<<<grid, block>>>(feat[l], LBs[l], HWs[l]);
    }

    // 2) per-anchor setup
    setup_kernel<<<NA, 128>>>(inst, anchor, proj, wh, Wl, bl);

    // 3) weight logits GEMM: (4096x256) @ (256x2496) -> g_logits (mode 1)
    {
        dim3 grid(NWTS / 64, NA / 128);
        sgemm_kernel<<<grid, 256>>>(inst, Ww, nullptr, NA, NWTS, ED, bw, nullptr, 1);
    }

    // 4) fused softmax + compacted aggregation (fp8 features)
    agg_kernel<<<NA, 256>>>();

    // 5) output GEMM: g_feats (mode 2) @ (256x256) + b_out + inst -> d_out
    {
        dim3 grid(ED / 64, NA / 128);
        sgemm_kernel<<<grid, 256>>>(nullptr, Wo, out, NA, ED, ED, bo, inst, 2);
    }
}

// round 8
// speedup vs baseline: 2.5264x; 1.3196x over previous
#include <cuda_runtime.h>
#include <cuda_fp16.h>
#include <cuda_bf16.h>
#include <cuda_fp8.h>
#include <math.h>
#include <stdint.h>

// ---------------------------------------------------------------------------
// Problem constants (fixed by the reference)
// ---------------------------------------------------------------------------
#define NA        4096
#define ED        256      // EMBED_DIMS
#define NG        8        // NUM_GROUPS
#define GD        32       // GROUP_DIMS
#define NL        4        // NUM_LEVELS
#define NC        6        // NUM_CAMS
#define NPT       13       // NUM_PTS (7 fixed + 6 learnable)
#define NSAMP     312      // NC*NL*NPT
#define NWTS      2496     // NSAMP*NG
#define MAXCOR    1280     // >= NSAMP*4

// level dims
__constant__ int   c_LW[4] = {176, 88, 44, 22};
__constant__ int   c_LH[4] = {64, 32, 16, 8};
__constant__ unsigned c_LB[4] = {0u, 17301504u, 21626880u, 22708224u};  // byte offsets (1B/elem)

__constant__ float c_fix[21] = {
    0.f,0.f,0.f,  0.45f,0.f,0.f,  -0.45f,0.f,0.f,
    0.f,0.45f,0.f, 0.f,-0.45f,0.f, 0.f,0.f,0.45f, 0.f,0.f,-0.45f
};

// ---------------------------------------------------------------------------
// Scratch (static __device__ — device-code references ONLY; host-side address
// of a __device__ symbol is the host shadow and silently "works" via ATS).
// g_f8 MUST be 16B-aligned: it is accessed through uint2* (8B vector loads).
// ---------------------------------------------------------------------------
__device__ __align__(16) unsigned char g_f8[22978560]; // 4 levels, NHWC, fp8 e4m3
__device__ float  g_logits[NA * NWTS];      // weight logits (softmaxed in agg)
__device__ float  g_p2d[NA * NPT * NC * 2]; // projected points
__device__ float  g_feats[NA * ED];         // aggregated features

// ---------------------------------------------------------------------------
// 1) CHW -> HWC transpose + fp32->fp8(e4m3) convert (per level).
// ---------------------------------------------------------------------------
__global__ void transpose_chw_hwc(const float* __restrict__ src, unsigned dst_base, int HW) {
    __shared__ float tile[32][33];
    int cam = blockIdx.z;
    int hw0 = blockIdx.x * 32;
    int c0  = blockIdx.y * 32;
    const float* s = src + (size_t)cam * ED * HW;
    unsigned char* d = g_f8 + dst_base + (size_t)cam * HW * ED;
    int tx = threadIdx.x, ty = threadIdx.y;
#pragma unroll
    for (int i = 0; i < 32; i += 8) {
        int c  = c0 + ty + i;
        int hw = hw0 + tx;
        float v = (hw < HW) ? s[(size_t)c * HW + hw] : 0.f;
        tile[ty + i][tx] = v;
    }
    __syncthreads();
#pragma unroll
    for (int i = 0; i < 32; i += 8) {
        int hw = hw0 + ty + i;
        int c  = c0 + tx;
        if (hw < HW)
            d[(size_t)hw * ED + c] =
                (unsigned char)__nv_cvt_float_to_fp8(tile[tx][ty + i], __NV_SATFINITE, __NV_E4M3);
    }
}

// ---------------------------------------------------------------------------
// 2) Per-anchor setup: learnable points, rotation, projection -> g_p2d
// ---------------------------------------------------------------------------
__global__ void __launch_bounds__(128) setup_kernel(
    const float* __restrict__ inst, const float* __restrict__ anchor,
    const float* __restrict__ proj, const float* __restrict__ wh,
    const float* __restrict__ Wl, const float* __restrict__ bl)
{
    int a = blockIdx.x;
    int tid = threadIdx.x;
    __shared__ float sif[ED];
    __shared__ float sscale[NPT * 3];
    __shared__ float skp[NPT * 3];
    __shared__ float sR[9];
    __shared__ float sts[6];

    const float* f = inst + (size_t)a * ED;
    sif[tid]       = f[tid];
    sif[tid + 128] = f[tid + 128];
    if (tid < 21) sscale[tid] = c_fix[tid];
    __syncthreads();

    const float* an = anchor + (size_t)a * 11;

    if (tid < 18) {
        float acc = bl[tid];
#pragma unroll 8
        for (int i = 0; i < ED; i++) acc = fmaf(sif[i], Wl[i * 18 + tid], acc);
        acc = fminf(fmaxf(acc, -9.21f), 9.21f);
        float sg = 1.f / (1.f + expf(-acc));
        sscale[21 + tid] = sg - 0.5f;
    }
    if (tid == 32) {
        float t0 = an[0], t1 = an[1], t2 = an[2];
        float s0 = an[3], s1 = an[4], s2 = an[5];
        float qw = an[6], qx = an[7], qy = an[8], qz = an[9];
        float inv = rsqrtf(qw*qw + qx*qx + qy*qy + qz*qz);
        qw *= inv; qx *= inv; qy *= inv; qz *= inv;
        float R00 = 1.f - 2.f*(qy*qy + qz*qz), R01 = 2.f*(qx*qy - qw*qz), R02 = 2.f*(qx*qz + qw*qy);
        float R10 = 2.f*(qx*qy + qw*qz), R11 = 1.f - 2.f*(qx*qx + qz*qz), R12 = 2.f*(qy*qz - qw*qx);
        float R20 = 2.f*(qx*qz - qw*qy), R21 = 2.f*(qy*qz + qw*qx), R22 = 1.f - 2.f*(qx*qx + qy*qy);
        sR[0] = R00; sR[1] = R10; sR[2] = R20;
        sR[3] = R01; sR[4] = R11; sR[5] = R21;
        sR[6] = R02; sR[7] = R12; sR[8] = R22;
        sts[0] = t0; sts[1] = t1; sts[2] = t2;
        sts[3] = s0; sts[4] = s1; sts[5] = s2;
    }
    __syncthreads();
    if (tid < NPT) {
        float v0 = sscale[tid*3+0] * sts[3];
        float v1 = sscale[tid*3+1] * sts[4];
        float v2 = sscale[tid*3+2] * sts[5];
        skp[tid*3+0] = sR[0]*v0 + sR[1]*v1 + sR[2]*v2 + sts[0];
        skp[tid*3+1] = sR[3]*v0 + sR[4]*v1 + sR[5]*v2 + sts[1];
        skp[tid*3+2] = sR[6]*v0 + sR[7]*v1 + sR[8]*v2 + sts[2];
    }
    __syncthreads();
    if (tid < NPT * NC) {
        int pt = tid / NC, cam = tid % NC;
        float x = skp[pt*3+0], y = skp[pt*3+1], z = skp[pt*3+2];
        const float* P = proj + cam * 16;
        float px = P[0]*x + P[1]*y + P[2]*z  + P[3];
        float py = P[4]*x + P[5]*y + P[6]*z  + P[7];
        float pz = P[8]*x + P[9]*y + P[10]*z + P[11];
        pz = fmaxf(pz, 1e-5f);
        float u = (px / pz) / wh[cam*2+0];
        float v = (py / pz) / wh[cam*2+1];
        u = fminf(fmaxf(u, 0.f), 0.9999f);
        v = fminf(fmaxf(v, 0.f), 0.9999f);
        g_p2d[((size_t)a * (NPT*NC) + tid) * 2 + 0] = u;
        g_p2d[((size_t)a * (NPT*NC) + tid) * 2 + 1] = v;
    }
}

// ---------------------------------------------------------------------------
// 3) Logits GEMM on tensor cores: g_logits = inst @ Ww + bw
//    mma.sync.m16n8k16 bf16, fp32 accumulate.
//    BM=128 BN=64 BK=64; 256 threads = 8 warps (4 m-quadrants x 2 n-halves).
// ---------------------------------------------------------------------------
__global__ void __launch_bounds__(256) gemm_bf16_logits(
    const float* __restrict__ A, const float* __restrict__ Bm,
    const float* __restrict__ bias)
{
    float* C = g_logits;                  // device-side symbol resolution
    const int M = NA, N = NWTS, K = ED;
    __shared__ __nv_bfloat16 As[128][72];   // +8 pad: conflict-free fragment loads
    __shared__ __nv_bfloat16 Bst[64][72];   // B stored transposed [n][k]

    int tid = threadIdx.x;
    int lane = tid & 31, w = tid >> 5;
    int wm = w & 3, wn = w >> 2;            // warp tile: rows wm*32+.., cols wn*32+..
    int m0 = blockIdx.y * 128, n0 = blockIdx.x * 64;
    int g = lane >> 2, t = lane & 3;

    float d[2][4][4];
#pragma unroll
    for (int mt = 0; mt < 2; mt++)
#pragma unroll
        for (int nt = 0; nt < 4; nt++)
#pragma unroll
            for (int r = 0; r < 4; r++) d[mt][nt][r] = 0.f;

    for (int k0 = 0; k0 < K; k0 += 64) {
        // load A 128x64 (coalesced rows), convert fp32->bf16
#pragma unroll
        for (int i = 0; i < 32; i++) {
            int e = i * 256 + tid;
            int row = e >> 6, kk = e & 63;
            As[row][kk] = __float2bfloat16(A[(size_t)(m0 + row) * K + k0 + kk]);
        }
        // load B 64x64 transposed into Bst[n][k]
#pragma unroll
        for (int i = 0; i < 16; i++) {
            int e = i * 256 + tid;
            int kk = e >> 6, n = e & 63;
            Bst[n][kk] = __float2bfloat16(Bm[(size_t)(k0 + kk) * N + n0 + n]);
        }
        __syncthreads();
#pragma unroll
        for (int ks = 0; ks < 4; ks++) {
            int kb = ks * 16;
            unsigned a[2][4], b[4][2];
#pragma unroll
            for (int mt = 0; mt < 2; mt++) {
                int rb = wm * 32 + mt * 16;
                a[mt][0] = *(const unsigned*)&As[rb + g][kb + 2 * t];
                a[mt][1] = *(const unsigned*)&As[rb + g + 8][kb + 2 * t];
                a[mt][2] = *(const unsigned*)&As[rb + g][kb + 2 * t + 8];
                a[mt][3] = *(const unsigned*)&As[rb + g + 8][kb + 2 * t + 8];
            }
#pragma unroll
            for (int nt = 0; nt < 4; nt++) {
                int cb = wn * 32 + nt * 8;
                b[nt][0] = *(const unsigned*)&Bst[cb + g][kb + 2 * t];
                b[nt][1] = *(const unsigned*)&Bst[cb + g][kb + 2 * t + 8];
            }
#pragma unroll
            for (int mt = 0; mt < 2; mt++)
#pragma unroll
                for (int nt = 0; nt < 4; nt++)
                    asm volatile(
                        "mma.sync.aligned.m16n8k16.row.col.f32.bf16.bf16.f32 "
                        "{%0,%1,%2,%3}, {%4,%5,%6,%7}, {%8,%9}, {%0,%1,%2,%3};"
                        : "+f"(d[mt][nt][0]), "+f"(d[mt][nt][1]),
                          "+f"(d[mt][nt][2]), "+f"(d[mt][nt][3])
                        : "r"(a[mt][0]), "r"(a[mt][1]), "r"(a[mt][2]), "r"(a[mt][3]),
                          "r"(b[nt][0]), "r"(b[nt][1]));
        }
        __syncthreads();
    }
    // epilogue: D[g][2t], D[g][2t+1], D[g+8][2t], D[g+8][2t+1] per (mt,nt)
#pragma unroll
    for (int mt = 0; mt < 2; mt++) {
        int rb = m0 + wm * 32 + mt * 16;
#pragma unroll
        for (int nt = 0; nt < 4; nt++) {
            int n = n0 + wn * 32 + nt * 8 + 2 * t;
            float b0 = bias[n], b1 = bias[n + 1];
            C[(size_t)(rb + g) * N + n]         = d[mt][nt][0] + b0;
            C[(size_t)(rb + g) * N + n + 1]     = d[mt][nt][1] + b1;
            C[(size_t)(rb + g + 8) * N + n]     = d[mt][nt][2] + b0;
            C[(size_t)(rb + g + 8) * N + n + 1] = d[mt][nt][3] + b1;
        }
    }
}

// ---------------------------------------------------------------------------
// 5) Out GEMM (f32x2 packed FMA): d_out = g_feats @ Wo + bo + inst
// ---------------------------------------------------------------------------
__global__ void __launch_bounds__(256) sgemm_kernel(
    const float* __restrict__ A, const float* __restrict__ B, float* __restrict__ C,
    int M, int N, int K, const float* __restrict__ bias, const float* __restrict__ res,
    int mode)
{
    if (mode == 2) A = g_feats;

    const int BM = 128, BN = 64, BK = 16;
    __shared__ float2 Asd[BK][BM + 2];
    __shared__ float  Bs[BK][BN];
    int tid = threadIdx.x;
    int tx = tid & 15, ty = tid >> 4;
    int m0 = blockIdx.y * BM, n0 = blockIdx.x * BN;

    unsigned long long acc[8][2];
#pragma unroll
    for (int x = 0; x < 8; x++) { acc[x][0] = 0ull; acc[x][1] = 0ull; }

    for (int k0 = 0; k0 < K; k0 += BK) {
#pragma unroll
        for (int i = 0; i < 8; i++) {
            int e = tid + i * 256;
            int m = e >> 4, kk = e & 15;
            float v = A[(size_t)(m0 + m) * K + k0 + kk];
            Asd[kk][m] = make_float2(v, v);
        }
#pragma unroll
        for (int i = 0; i < 4; i++) {
            int e = tid + i * 256;
            int kk = e >> 6, n = e & 63;
            Bs[kk][n] = B[(size_t)(k0 + kk) * N + n0 + n];
        }
        __syncthreads();
#pragma unroll
        for (int kk = 0; kk < BK; kk++) {
            unsigned long long av[8], bv[2];
            const ulonglong2* ap = (const ulonglong2*)&Asd[kk][ty * 8];
            ulonglong2 t;
            t = ap[0]; av[0] = t.x; av[1] = t.y;
            t = ap[1]; av[2] = t.x; av[3] = t.y;
            t = ap[2]; av[4] = t.x; av[5] = t.y;
            t = ap[3]; av[6] = t.x; av[7] = t.y;
            ulonglong2 bq = *(const ulonglong2*)&Bs[kk][tx * 4];
            bv[0] = bq.x; bv[1] = bq.y;
#pragma unroll
            for (int x = 0; x < 8; x++) {
                asm("fma.rn.f32x2 %0, %1, %2, %0;" : "+l"(acc[x][0]) : "l"(av[x]), "l"(bv[0]));
                asm("fma.rn.f32x2 %0, %1, %2, %0;" : "+l"(acc[x][1]) : "l"(av[x]), "l"(bv[1]));
            }
        }
        __syncthreads();
    }
#pragma unroll
    for (int x = 0; x < 8; x++) {
        int m = m0 + ty * 8 + x;
#pragma unroll
        for (int y = 0; y < 2; y++) {
            unsigned long long u = acc[x][y];
            float v0 = __uint_as_float((unsigned)u);
            float v1 = __uint_as_float((unsigned)(u >> 32));
            int n = n0 + tx * 4 + y * 2;
            if (bias) { v0 += bias[n]; v1 += bias[n + 1]; }
            if (res)  { v0 += res[(size_t)m * N + n]; v1 += res[(size_t)m * N + n + 1]; }
            C[(size_t)m * N + n]     = v0;
            C[(size_t)m * N + n + 1] = v1;
        }
    }
}

// ---------------------------------------------------------------------------
// per-sample bilinear corner metadata (shared by count & fill passes)
// ---------------------------------------------------------------------------
struct Corners {
    unsigned o[4];   // uint2-unit offsets (8 fp8 bytes per unit)
    float    w[4];   // bilinear weights (0 if invalid)
};

__device__ __forceinline__ Corners corner_meta(float2 p, int s) {
    int cam = s / (NL * NPT);
    int rr  = s % (NL * NPT);
    int lvl = rr / NPT;
    Corners r;
    int W = c_LW[lvl], H = c_LH[lvl];
    float x = p.x * (float)W - 0.5f;
    float y = p.y * (float)H - 0.5f;
    float xf = floorf(x), yf = floorf(y);
    float wx = x - xf, wy = y - yf;
    int x0 = (int)xf, y0 = (int)yf;
    int x1 = x0 + 1, y1 = y0 + 1;
    bool vx0 = (x0 >= 0) & (x0 < W);
    bool vx1 = (x1 >= 0) & (x1 < W);
    bool vy0 = (y0 >= 0) & (y0 < H);
    bool vy1 = (y1 >= 0) & (y1 < H);
    r.w[0] = (vx0 && vy0) ? (1.f - wx) * (1.f - wy) : 0.f;
    r.w[1] = (vx1 && vy0) ? wx * (1.f - wy) : 0.f;
    r.w[2] = (vx0 && vy1) ? (1.f - wx) * wy : 0.f;
    r.w[3] = (vx1 && vy1) ? wx * wy : 0.f;
    int x0c = min(max(x0, 0), W - 1), x1c = min(max(x1, 0), W - 1);
    int y0c = min(max(y0, 0), H - 1), y1c = min(max(y1, 0), H - 1);
    unsigned lb = c_LB[lvl];
    unsigned rowb = (unsigned)(cam * H);
    r.o[0] = (lb + ((rowb + (unsigned)y0c) * (unsigned)W + (unsigned)x0c) * 256u) >> 3;
    r.o[1] = (lb + ((rowb + (unsigned)y0c) * (unsigned)W + (unsigned)x1c) * 256u) >> 3;
    r.o[2] = (lb + ((rowb + (unsigned)y1c) * (unsigned)W + (unsigned)x0c) * 256u) >> 3;
    r.o[3] = (lb + ((rowb + (unsigned)y1c) * (unsigned)W + (unsigned)x1c) * 256u) >> 3;
    return r;
}

// decode 4 packed e4m3 -> float4
__device__ __forceinline__ float4 fp8x4_to_float4(unsigned v) {
    __half2_raw h01 = __nv_cvt_fp8x2_to_halfraw2((__nv_fp8x2_storage_t)(v & 0xffffu), __NV_E4M3);
    __half2_raw h23 = __nv_cvt_fp8x2_to_halfraw2((__nv_fp8x2_storage_t)(v >> 16), __NV_E4M3);
    float2 a = __half22float2(*reinterpret_cast<__half2*>(&h01));
    float2 b = __half22float2(*reinterpret_cast<__half2*>(&h23));
    return make_float4(a.x, a.y, b.x, b.y);
}

// ---------------------------------------------------------------------------
// 4) Fused softmax + compacted bilinear aggregation (fp8 features).
// ---------------------------------------------------------------------------
__global__ void __launch_bounds__(256) agg_kernel() {
    int a = blockIdx.x;
    int tid = threadIdx.x;
    int lane = tid & 31, warp = tid >> 5;

    __shared__ float  sw[NWTS];
    __shared__ float2 sp2[NPT * NC];
    __shared__ unsigned fo[MAXCOR];
    __shared__ float2   fm[MAXCOR];
    __shared__ int scnt[320];
    __shared__ int sbase[NSAMP];
    __shared__ int sT;
    __shared__ __align__(16) float spart[8 * ED];

    const float* lrow = g_logits + (size_t)a * NWTS;
    for (int i = tid; i < NWTS; i += 256) sw[i] = lrow[i];
    if (tid < NPT * NC) sp2[tid] = ((const float2*)g_p2d)[(size_t)a * (NPT*NC) + tid];
    if (tid >= NSAMP && tid < 320) scnt[tid] = 0;
    __syncthreads();

    // per-group softmax over 312 entries (warp g handles group g)
    {
        int g = warp;
        float m = -1e30f;
        for (int i = lane; i < NSAMP; i += 32) m = fmaxf(m, sw[i * NG + g]);
#pragma unroll
        for (int o = 16; o > 0; o >>= 1) m = fmaxf(m, __shfl_xor_sync(0xffffffffu, m, o));
        float ssum = 0.f;
        for (int i = lane; i < NSAMP; i += 32) {
            float e = __expf(sw[i * NG + g] - m);
            sw[i * NG + g] = e;
            ssum += e;
        }
#pragma unroll
        for (int o = 16; o > 0; o >>= 1) ssum += __shfl_xor_sync(0xffffffffu, ssum, o);
        float inv = 1.f / ssum;
        for (int i = lane; i < NSAMP; i += 32) sw[i * NG + g] *= inv;
    }

    // pass 1: per-sample valid-corner counts
    for (int s = tid; s < NSAMP; s += 256) {
        int pt = (s % (NL * NPT)) % NPT, cam = s / (NL * NPT);
        Corners cr = corner_meta(sp2[pt * NC + cam], s);
        scnt[s] = (cr.w[0] != 0.f) + (cr.w[1] != 0.f) + (cr.w[2] != 0.f) + (cr.w[3] != 0.f);
    }
    __syncthreads();

    // deterministic exclusive scan over 312 counts
    if (tid < 32) {
        int l = tid;
        int tot = 0;
#pragma unroll
        for (int k = 0; k < 10; k++) {
            int s = l * 10 + k;
            tot += (s < NSAMP) ? scnt[s] : 0;
        }
        int inc = tot;
#pragma unroll
        for (int o = 1; o < 32; o <<= 1) {
            int v = __shfl_up_sync(0xffffffffu, inc, o);
            if (l >= o) inc += v;
        }
        int run = inc - tot;
#pragma unroll
        for (int k = 0; k < 10; k++) {
            int s = l * 10 + k;
            if (s < NSAMP) { sbase[s] = run; run += scnt[s]; }
        }
        if (l == 31) sT = run;
    }
    __syncthreads();

    // pass 2: fill compacted corner list
    for (int s = tid; s < NSAMP; s += 256) {
        int pt = (s % (NL * NPT)) % NPT, cam = s / (NL * NPT);
        Corners cr = corner_meta(sp2[pt * NC + cam], s);
        int b = sbase[s];
        float widx = __int_as_float(s * NG);
#pragma unroll
        for (int k = 0; k < 4; k++) {
            if (cr.w[k] != 0.f) {
                fo[b] = cr.o[k];
                fm[b] = make_float2(cr.w[k], widx);
                b++;
            }
        }
    }
    __syncthreads();

    const int T = sT;
    int g = lane >> 2;
    float acc0 = 0.f, acc1 = 0.f, acc2 = 0.f, acc3 = 0.f;
    float acc4 = 0.f, acc5 = 0.f, acc6 = 0.f, acc7 = 0.f;
    const uint2* __restrict__ F8 = (const uint2*)g_f8;
#pragma unroll 4
    for (int j = warp; j < T; j += 8) {
        unsigned o = fo[j];
        float2 m = fm[j];
        float w = sw[__float_as_int(m.y) + g] * m.x;
        uint2 u = __ldg(F8 + o + lane);
        float4 fa = fp8x4_to_float4(u.x);
        float4 fb = fp8x4_to_float4(u.y);
        acc0 = fmaf(w, fa.x, acc0);
        acc1 = fmaf(w, fa.y, acc1);
        acc2 = fmaf(w, fa.z, acc2);
        acc3 = fmaf(w, fa.w, acc3);
        acc4 = fmaf(w, fb.x, acc4);
        acc5 = fmaf(w, fb.y, acc5);
        acc6 = fmaf(w, fb.z, acc6);
        acc7 = fmaf(w, fb.w, acc7);
    }
    {
        float4* sp4 = (float4*)&spart[warp * ED + lane * 8];
        sp4[0] = make_float4(acc0, acc1, acc2, acc3);
        sp4[1] = make_float4(acc4, acc5, acc6, acc7);
    }
    __syncthreads();
    {
        int ch = tid;
        float r = spart[ch];
#pragma unroll
        for (int p = 1; p < 8; p++) r += spart[p * ED + ch];
        g_feats[(size_t)a * ED + ch] = r;
    }
}

// ---------------------------------------------------------------------------
// launch — inputs bound by unique element counts (order-proof)
// ---------------------------------------------------------------------------
extern "C" void kernel_launch(void* const* d_in, const int* in_sizes, int n_in,
                              void* d_out, int out_size) {
    const float* inst = 0; const float* anchor = 0;
    const float* feat[4] = {0,0,0,0};
    const float* proj = 0; const float* wh = 0;
    const float* Wl = 0; const float* bl = 0;
    const float* Ww = 0; const float* bw = 0;
    const float* Wo = 0; const float* bo = 0;

    for (int i = 0; i < n_in; i++) {
        const float* p = (const float*)d_in[i];
        switch (in_sizes[i]) {
            case 1048576:  inst    = p; break;  // (1,4096,256)
            case 45056:    anchor  = p; break;  // (1,4096,11)
            case 17301504: feat[0] = p; break;
            case 4325376:  feat[1] = p; break;
            case 1081344:  feat[2] = p; break;
            case 270336:   feat[3] = p; break;
            case 96:       proj    = p; break;  // (1,6,4,4)
            case 12:       wh      = p; break;  // (1,6,2)
            case 4608:     Wl      = p; break;  // (256,18)
            case 18:       bl      = p; break;
            case 638976:   Ww      = p; break;  // (256,2496)
            case 2496:     bw      = p; break;
            case 65536:    Wo      = p; break;  // (256,256)
            case 256:      bo      = p; break;
            default: break;                      // pts3d unused
        }
    }
    float* out = (float*)d_out;

    // 1) transposes + fp8 convert
    const int HWs[4] = {64 * 176, 32 * 88, 16 * 44, 8 * 22};
    const unsigned LBs[4] = {0u, 17301504u, 21626880u, 22708224u};
    for (int l = 0; l < 4; l++) {
        dim3 grid((HWs[l] + 31) / 32, ED / 32, NC);
        dim3 block(32, 8);
        transpose_chw_hwc<<<grid, block>>>(feat[l], LBs[l], HWs[l]);
    }

    // 2) per-anchor setup
    setup_kernel<<<NA, 128>>>(inst, anchor, proj, wh, Wl, bl);

    // 3) weight logits GEMM on tensor cores: (4096x256) @ (256x2496) -> g_logits
    {
        dim3 grid(NWTS / 64, NA / 128);
        gemm_bf16_logits<<<grid, 256>>>(inst, Ww, bw);
    }

    // 4) fused softmax + compacted aggregation (fp8 features)
    agg_kernel<<<NA, 256>>>();

    // 5) output GEMM: g_feats (mode 2) @ (256x256) + b_out + inst -> d_out
    {
        dim3 grid(ED / 64, NA / 128);
        sgemm_kernel<<<grid, 256>>>(nullptr, Wo, out, NA, ED, ED, bo, inst, 2);
    }
}

// round 9
// speedup vs baseline: 2.8083x; 1.1116x over previous
#include <cuda_runtime.h>
#include <cuda_fp16.h>
#include <cuda_bf16.h>
#include <cuda_fp8.h>
#include <math.h>
#include <stdint.h>

// ---------------------------------------------------------------------------
// Problem constants (fixed by the reference)
// ---------------------------------------------------------------------------
#define NA        4096
#define ED        256      // EMBED_DIMS
#define NG        8        // NUM_GROUPS
#define GD        32       // GROUP_DIMS
#define NL        4        // NUM_LEVELS
#define NC        6        // NUM_CAMS
#define NPT       13       // NUM_PTS (7 fixed + 6 learnable)
#define NSAMP     312      // NC*NL*NPT
#define NSAMPP    313      // padded (bank destagger)
#define NWTS      2496     // NSAMP*NG
#define MAXCOR    1280     // >= NSAMP*4

// level dims
__constant__ int   c_LW[4] = {176, 88, 44, 22};
__constant__ int   c_LH[4] = {64, 32, 16, 8};
__constant__ unsigned c_LB[4] = {0u, 17301504u, 21626880u, 22708224u};  // byte offsets (1B/elem)

__constant__ float c_fix[21] = {
    0.f,0.f,0.f,  0.45f,0.f,0.f,  -0.45f,0.f,0.f,
    0.f,0.45f,0.f, 0.f,-0.45f,0.f, 0.f,0.f,0.45f, 0.f,0.f,-0.45f
};

// ---------------------------------------------------------------------------
// Scratch (static __device__ — device-code references ONLY; host-side address
// of a __device__ symbol is the host shadow and silently "works" via ATS).
// ---------------------------------------------------------------------------
__device__ __align__(16) unsigned char g_f8[22978560]; // 4 levels, NHWC, fp8 e4m3
__device__ float  g_logits[NA * NWTS];      // weight logits (softmaxed in agg)
__device__ float  g_p2d[NA * NPT * NC * 2]; // projected points
__device__ float  g_feats[NA * ED];         // aggregated features

// ---------------------------------------------------------------------------
// 1) CHW -> HWC transpose + fp32->fp8(e4m3) convert (per level).
// ---------------------------------------------------------------------------
__global__ void transpose_chw_hwc(const float* __restrict__ src, unsigned dst_base, int HW) {
    __shared__ float tile[32][33];
    int cam = blockIdx.z;
    int hw0 = blockIdx.x * 32;
    int c0  = blockIdx.y * 32;
    const float* s = src + (size_t)cam * ED * HW;
    unsigned char* d = g_f8 + dst_base + (size_t)cam * HW * ED;
    int tx = threadIdx.x, ty = threadIdx.y;
#pragma unroll
    for (int i = 0; i < 32; i += 8) {
        int c  = c0 + ty + i;
        int hw = hw0 + tx;
        float v = (hw < HW) ? s[(size_t)c * HW + hw] : 0.f;
        tile[ty + i][tx] = v;
    }
    __syncthreads();
#pragma unroll
    for (int i = 0; i < 32; i += 8) {
        int hw = hw0 + ty + i;
        int c  = c0 + tx;
        if (hw < HW)
            d[(size_t)hw * ED + c] =
                (unsigned char)__nv_cvt_float_to_fp8(tile[tx][ty + i], __NV_SATFINITE, __NV_E4M3);
    }
}

// ---------------------------------------------------------------------------
// 2) Per-anchor setup: learnable points, rotation, projection -> g_p2d
// ---------------------------------------------------------------------------
__global__ void __launch_bounds__(128) setup_kernel(
    const float* __restrict__ inst, const float* __restrict__ anchor,
    const float* __restrict__ proj, const float* __restrict__ wh,
    const float* __restrict__ Wl, const float* __restrict__ bl)
{
    int a = blockIdx.x;
    int tid = threadIdx.x;
    __shared__ float sif[ED];
    __shared__ float sscale[NPT * 3];
    __shared__ float skp[NPT * 3];
    __shared__ float sR[9];
    __shared__ float sts[6];

    const float* f = inst + (size_t)a * ED;
    sif[tid]       = f[tid];
    sif[tid + 128] = f[tid + 128];
    if (tid < 21) sscale[tid] = c_fix[tid];
    __syncthreads();

    const float* an = anchor + (size_t)a * 11;

    if (tid < 18) {
        float acc = bl[tid];
#pragma unroll 8
        for (int i = 0; i < ED; i++) acc = fmaf(sif[i], Wl[i * 18 + tid], acc);
        acc = fminf(fmaxf(acc, -9.21f), 9.21f);
        float sg = 1.f / (1.f + expf(-acc));
        sscale[21 + tid] = sg - 0.5f;
    }
    if (tid == 32) {
        float t0 = an[0], t1 = an[1], t2 = an[2];
        float s0 = an[3], s1 = an[4], s2 = an[5];
        float qw = an[6], qx = an[7], qy = an[8], qz = an[9];
        float inv = rsqrtf(qw*qw + qx*qx + qy*qy + qz*qz);
        qw *= inv; qx *= inv; qy *= inv; qz *= inv;
        float R00 = 1.f - 2.f*(qy*qy + qz*qz), R01 = 2.f*(qx*qy - qw*qz), R02 = 2.f*(qx*qz + qw*qy);
        float R10 = 2.f*(qx*qy + qw*qz), R11 = 1.f - 2.f*(qx*qx + qz*qz), R12 = 2.f*(qy*qz - qw*qx);
        float R20 = 2.f*(qx*qz - qw*qy), R21 = 2.f*(qy*qz + qw*qx), R22 = 1.f - 2.f*(qx*qx + qy*qy);
        sR[0] = R00; sR[1] = R10; sR[2] = R20;
        sR[3] = R01; sR[4] = R11; sR[5] = R21;
        sR[6] = R02; sR[7] = R12; sR[8] = R22;
        sts[0] = t0; sts[1] = t1; sts[2] = t2;
        sts[3] = s0; sts[4] = s1; sts[5] = s2;
    }
    __syncthreads();
    if (tid < NPT) {
        float v0 = sscale[tid*3+0] * sts[3];
        float v1 = sscale[tid*3+1] * sts[4];
        float v2 = sscale[tid*3+2] * sts[5];
        skp[tid*3+0] = sR[0]*v0 + sR[1]*v1 + sR[2]*v2 + sts[0];
        skp[tid*3+1] = sR[3]*v0 + sR[4]*v1 + sR[5]*v2 + sts[1];
        skp[tid*3+2] = sR[6]*v0 + sR[7]*v1 + sR[8]*v2 + sts[2];
    }
    __syncthreads();
    if (tid < NPT * NC) {
        int pt = tid / NC, cam = tid % NC;
        float x = skp[pt*3+0], y = skp[pt*3+1], z = skp[pt*3+2];
        const float* P = proj + cam * 16;
        float px = P[0]*x + P[1]*y + P[2]*z  + P[3];
        float py = P[4]*x + P[5]*y + P[6]*z  + P[7];
        float pz = P[8]*x + P[9]*y + P[10]*z + P[11];
        pz = fmaxf(pz, 1e-5f);
        float u = (px / pz) / wh[cam*2+0];
        float v = (py / pz) / wh[cam*2+1];
        u = fminf(fmaxf(u, 0.f), 0.9999f);
        v = fminf(fmaxf(v, 0.f), 0.9999f);
        g_p2d[((size_t)a * (NPT*NC) + tid) * 2 + 0] = u;
        g_p2d[((size_t)a * (NPT*NC) + tid) * 2 + 1] = v;
    }
}

// ---------------------------------------------------------------------------
// 3) Logits GEMM on tensor cores: g_logits = inst @ Ww + bw
//    mma.sync.m16n8k16 bf16, fp32 accumulate.
// ---------------------------------------------------------------------------
__global__ void __launch_bounds__(256) gemm_bf16_logits(
    const float* __restrict__ A, const float* __restrict__ Bm,
    const float* __restrict__ bias)
{
    float* C = g_logits;
    const int N = NWTS, K = ED;
    __shared__ __nv_bfloat16 As[128][72];
    __shared__ __nv_bfloat16 Bst[64][72];

    int tid = threadIdx.x;
    int lane = tid & 31, w = tid >> 5;
    int wm = w & 3, wn = w >> 2;
    int m0 = blockIdx.y * 128, n0 = blockIdx.x * 64;
    int g = lane >> 2, t = lane & 3;

    float d[2][4][4];
#pragma unroll
    for (int mt = 0; mt < 2; mt++)
#pragma unroll
        for (int nt = 0; nt < 4; nt++)
#pragma unroll
            for (int r = 0; r < 4; r++) d[mt][nt][r] = 0.f;

    for (int k0 = 0; k0 < K; k0 += 64) {
#pragma unroll
        for (int i = 0; i < 32; i++) {
            int e = i * 256 + tid;
            int row = e >> 6, kk = e & 63;
            As[row][kk] = __float2bfloat16(A[(size_t)(m0 + row) * K + k0 + kk]);
        }
#pragma unroll
        for (int i = 0; i < 16; i++) {
            int e = i * 256 + tid;
            int kk = e >> 6, n = e & 63;
            Bst[n][kk] = __float2bfloat16(Bm[(size_t)(k0 + kk) * N + n0 + n]);
        }
        __syncthreads();
#pragma unroll
        for (int ks = 0; ks < 4; ks++) {
            int kb = ks * 16;
            unsigned a[2][4], b[4][2];
#pragma unroll
            for (int mt = 0; mt < 2; mt++) {
                int rb = wm * 32 + mt * 16;
                a[mt][0] = *(const unsigned*)&As[rb + g][kb + 2 * t];
                a[mt][1] = *(const unsigned*)&As[rb + g + 8][kb + 2 * t];
                a[mt][2] = *(const unsigned*)&As[rb + g][kb + 2 * t + 8];
                a[mt][3] = *(const unsigned*)&As[rb + g + 8][kb + 2 * t + 8];
            }
#pragma unroll
            for (int nt = 0; nt < 4; nt++) {
                int cb = wn * 32 + nt * 8;
                b[nt][0] = *(const unsigned*)&Bst[cb + g][kb + 2 * t];
                b[nt][1] = *(const unsigned*)&Bst[cb + g][kb + 2 * t + 8];
            }
#pragma unroll
            for (int mt = 0; mt < 2; mt++)
#pragma unroll
                for (int nt = 0; nt < 4; nt++)
                    asm volatile(
                        "mma.sync.aligned.m16n8k16.row.col.f32.bf16.bf16.f32 "
                        "{%0,%1,%2,%3}, {%4,%5,%6,%7}, {%8,%9}, {%0,%1,%2,%3};"
                        : "+f"(d[mt][nt][0]), "+f"(d[mt][nt][1]),
                          "+f"(d[mt][nt][2]), "+f"(d[mt][nt][3])
                        : "r"(a[mt][0]), "r"(a[mt][1]), "r"(a[mt][2]), "r"(a[mt][3]),
                          "r"(b[nt][0]), "r"(b[nt][1]));
        }
        __syncthreads();
    }
#pragma unroll
    for (int mt = 0; mt < 2; mt++) {
        int rb = m0 + wm * 32 + mt * 16;
#pragma unroll
        for (int nt = 0; nt < 4; nt++) {
            int n = n0 + wn * 32 + nt * 8 + 2 * t;
            float b0 = bias[n], b1 = bias[n + 1];
            C[(size_t)(rb + g) * N + n]         = d[mt][nt][0] + b0;
            C[(size_t)(rb + g) * N + n + 1]     = d[mt][nt][1] + b1;
            C[(size_t)(rb + g + 8) * N + n]     = d[mt][nt][2] + b0;
            C[(size_t)(rb + g + 8) * N + n + 1] = d[mt][nt][3] + b1;
        }
    }
}

// ---------------------------------------------------------------------------
// 5) Out GEMM (f32x2 packed FMA): d_out = g_feats @ Wo + bo + inst
// ---------------------------------------------------------------------------
__global__ void __launch_bounds__(256) sgemm_kernel(
    const float* __restrict__ A, const float* __restrict__ B, float* __restrict__ C,
    int M, int N, int K, const float* __restrict__ bias, const float* __restrict__ res,
    int mode)
{
    if (mode == 2) A = g_feats;

    const int BM = 128, BN = 64, BK = 16;
    __shared__ float2 Asd[BK][BM + 2];
    __shared__ float  Bs[BK][BN];
    int tid = threadIdx.x;
    int tx = tid & 15, ty = tid >> 4;
    int m0 = blockIdx.y * BM, n0 = blockIdx.x * BN;

    unsigned long long acc[8][2];
#pragma unroll
    for (int x = 0; x < 8; x++) { acc[x][0] = 0ull; acc[x][1] = 0ull; }

    for (int k0 = 0; k0 < K; k0 += BK) {
#pragma unroll
        for (int i = 0; i < 8; i++) {
            int e = tid + i * 256;
            int m = e >> 4, kk = e & 15;
            float v = A[(size_t)(m0 + m) * K + k0 + kk];
            Asd[kk][m] = make_float2(v, v);
        }
#pragma unroll
        for (int i = 0; i < 4; i++) {
            int e = tid + i * 256;
            int kk = e >> 6, n = e & 63;
            Bs[kk][n] = B[(size_t)(k0 + kk) * N + n0 + n];
        }
        __syncthreads();
#pragma unroll
        for (int kk = 0; kk < BK; kk++) {
            unsigned long long av[8], bv[2];
            const ulonglong2* ap = (const ulonglong2*)&Asd[kk][ty * 8];
            ulonglong2 t;
            t = ap[0]; av[0] = t.x; av[1] = t.y;
            t = ap[1]; av[2] = t.x; av[3] = t.y;
            t = ap[2]; av[4] = t.x; av[5] = t.y;
            t = ap[3]; av[6] = t.x; av[7] = t.y;
            ulonglong2 bq = *(const ulonglong2*)&Bs[kk][tx * 4];
            bv[0] = bq.x; bv[1] = bq.y;
#pragma unroll
            for (int x = 0; x < 8; x++) {
                asm("fma.rn.f32x2 %0, %1, %2, %0;" : "+l"(acc[x][0]) : "l"(av[x]), "l"(bv[0]));
                asm("fma.rn.f32x2 %0, %1, %2, %0;" : "+l"(acc[x][1]) : "l"(av[x]), "l"(bv[1]));
            }
        }
        __syncthreads();
    }
#pragma unroll
    for (int x = 0; x < 8; x++) {
        int m = m0 + ty * 8 + x;
#pragma unroll
        for (int y = 0; y < 2; y++) {
            unsigned long long u = acc[x][y];
            float v0 = __uint_as_float((unsigned)u);
            float v1 = __uint_as_float((unsigned)(u >> 32));
            int n = n0 + tx * 4 + y * 2;
            if (bias) { v0 += bias[n]; v1 += bias[n + 1]; }
            if (res)  { v0 += res[(size_t)m * N + n]; v1 += res[(size_t)m * N + n + 1]; }
            C[(size_t)m * N + n]     = v0;
            C[(size_t)m * N + n + 1] = v1;
        }
    }
}

// ---------------------------------------------------------------------------
// per-sample bilinear corner metadata (shared by count & fill passes)
// ---------------------------------------------------------------------------
struct Corners {
    unsigned o[4];   // uint2-unit offsets (8 fp8 bytes per unit)
    float    w[4];   // bilinear weights (0 if invalid)
};

__device__ __forceinline__ Corners corner_meta(float2 p, int s) {
    int cam = s / (NL * NPT);
    int rr  = s % (NL * NPT);
    int lvl = rr / NPT;
    Corners r;
    int W = c_LW[lvl], H = c_LH[lvl];
    float x = p.x * (float)W - 0.5f;
    float y = p.y * (float)H - 0.5f;
    float xf = floorf(x), yf = floorf(y);
    float wx = x - xf, wy = y - yf;
    int x0 = (int)xf, y0 = (int)yf;
    int x1 = x0 + 1, y1 = y0 + 1;
    bool vx0 = (x0 >= 0) & (x0 < W);
    bool vx1 = (x1 >= 0) & (x1 < W);
    bool vy0 = (y0 >= 0) & (y0 < H);
    bool vy1 = (y1 >= 0) & (y1 < H);
    r.w[0] = (vx0 && vy0) ? (1.f - wx) * (1.f - wy) : 0.f;
    r.w[1] = (vx1 && vy0) ? wx * (1.f - wy) : 0.f;
    r.w[2] = (vx0 && vy1) ? (1.f - wx) * wy : 0.f;
    r.w[3] = (vx1 && vy1) ? wx * wy : 0.f;
    int x0c = min(max(x0, 0), W - 1), x1c = min(max(x1, 0), W - 1);
    int y0c = min(max(y0, 0), H - 1), y1c = min(max(y1, 0), H - 1);
    unsigned lb = c_LB[lvl];
    unsigned rowb = (unsigned)(cam * H);
    r.o[0] = (lb + ((rowb + (unsigned)y0c) * (unsigned)W + (unsigned)x0c) * 256u) >> 3;
    r.o[1] = (lb + ((rowb + (unsigned)y0c) * (unsigned)W + (unsigned)x1c) * 256u) >> 3;
    r.o[2] = (lb + ((rowb + (unsigned)y1c) * (unsigned)W + (unsigned)x0c) * 256u) >> 3;
    r.o[3] = (lb + ((rowb + (unsigned)y1c) * (unsigned)W + (unsigned)x1c) * 256u) >> 3;
    return r;
}

// ---------------------------------------------------------------------------
// 4) Fused softmax + compacted bilinear aggregation (fp8 features, half2 MAC).
//    sw layout [g][NSAMPP] (conflict-free softmax); corner entries packed uint4.
// ---------------------------------------------------------------------------
__global__ void __launch_bounds__(256) agg_kernel() {
    int a = blockIdx.x;
    int tid = threadIdx.x;
    int lane = tid & 31, warp = tid >> 5;

    __shared__ float  sw[NG * NSAMPP];   // softmaxed weights, [g][s]
    __shared__ float2 sp2[NPT * NC];
    __shared__ __align__(16) uint4 flist[MAXCOR];  // (off, w_bits, s, pad)
    __shared__ int scnt[320];
    __shared__ int sbase[NSAMP];
    __shared__ int sT;
    __shared__ __align__(16) float spart[8 * ED];

    // load logits transposed: memory col = s*NG+g -> sw[g*NSAMPP+s]
    const float* lrow = g_logits + (size_t)a * NWTS;
    for (int i = tid; i < NWTS; i += 256) {
        int s = i >> 3, g = i & 7;
        sw[g * NSAMPP + s] = lrow[i];
    }
    if (tid < NPT * NC) sp2[tid] = ((const float2*)g_p2d)[(size_t)a * (NPT*NC) + tid];
    if (tid >= NSAMP && tid < 320) scnt[tid] = 0;
    __syncthreads();

    // per-group softmax over 312 entries (warp g handles group g; conflict-free)
    {
        float* swg = sw + warp * NSAMPP;
        float m = -1e30f;
        for (int i = lane; i < NSAMP; i += 32) m = fmaxf(m, swg[i]);
#pragma unroll
        for (int o = 16; o > 0; o >>= 1) m = fmaxf(m, __shfl_xor_sync(0xffffffffu, m, o));
        float ssum = 0.f;
        for (int i = lane; i < NSAMP; i += 32) {
            float e = __expf(swg[i] - m);
            swg[i] = e;
            ssum += e;
        }
#pragma unroll
        for (int o = 16; o > 0; o >>= 1) ssum += __shfl_xor_sync(0xffffffffu, ssum, o);
        float inv = 1.f / ssum;
        for (int i = lane; i < NSAMP; i += 32) swg[i] *= inv;
    }

    // pass 1: per-sample valid-corner counts
    for (int s = tid; s < NSAMP; s += 256) {
        int pt = (s % (NL * NPT)) % NPT, cam = s / (NL * NPT);
        Corners cr = corner_meta(sp2[pt * NC + cam], s);
        scnt[s] = (cr.w[0] != 0.f) + (cr.w[1] != 0.f) + (cr.w[2] != 0.f) + (cr.w[3] != 0.f);
    }
    __syncthreads();

    // deterministic exclusive scan over 312 counts
    if (tid < 32) {
        int l = tid;
        int tot = 0;
#pragma unroll
        for (int k = 0; k < 10; k++) {
            int s = l * 10 + k;
            tot += (s < NSAMP) ? scnt[s] : 0;
        }
        int inc = tot;
#pragma unroll
        for (int o = 1; o < 32; o <<= 1) {
            int v = __shfl_up_sync(0xffffffffu, inc, o);
            if (l >= o) inc += v;
        }
        int run = inc - tot;
#pragma unroll
        for (int k = 0; k < 10; k++) {
            int s = l * 10 + k;
            if (s < NSAMP) { sbase[s] = run; run += scnt[s]; }
        }
        if (l == 31) sT = run;
    }
    __syncthreads();

    // pass 2: fill compacted corner list
    for (int s = tid; s < NSAMP; s += 256) {
        int pt = (s % (NL * NPT)) % NPT, cam = s / (NL * NPT);
        Corners cr = corner_meta(sp2[pt * NC + cam], s);
        int b = sbase[s];
#pragma unroll
        for (int k = 0; k < 4; k++) {
            if (cr.w[k] != 0.f) {
                flist[b] = make_uint4(cr.o[k], __float_as_uint(cr.w[k]), (unsigned)s, 0u);
                b++;
            }
        }
    }
    __syncthreads();

    const int T = sT;
    int g = lane >> 2;
    const float* swg = sw + g * NSAMPP;
    __half2 h0 = __float2half2_rn(0.f), h1 = h0, h2a = h0, h3 = h0;
    const uint2* __restrict__ F8 = (const uint2*)g_f8;
#pragma unroll 4
    for (int j = warp; j < T; j += 8) {
        uint4 e = flist[j];                       // broadcast LDS.128
        float w = swg[e.z] * __uint_as_float(e.y);
        __half2 wh = __half2half2(__float2half_rn(w));
        uint2 u = __ldg(F8 + e.x + lane);
        __half2_raw r0 = __nv_cvt_fp8x2_to_halfraw2((__nv_fp8x2_storage_t)(u.x & 0xffffu), __NV_E4M3);
        __half2_raw r1 = __nv_cvt_fp8x2_to_halfraw2((__nv_fp8x2_storage_t)(u.x >> 16), __NV_E4M3);
        __half2_raw r2 = __nv_cvt_fp8x2_to_halfraw2((__nv_fp8x2_storage_t)(u.y & 0xffffu), __NV_E4M3);
        __half2_raw r3 = __nv_cvt_fp8x2_to_halfraw2((__nv_fp8x2_storage_t)(u.y >> 16), __NV_E4M3);
        h0  = __hfma2(wh, *reinterpret_cast<__half2*>(&r0), h0);
        h1  = __hfma2(wh, *reinterpret_cast<__half2*>(&r1), h1);
        h2a = __hfma2(wh, *reinterpret_cast<__half2*>(&r2), h2a);
        h3  = __hfma2(wh, *reinterpret_cast<__half2*>(&r3), h3);
    }
    {
        float2 f0 = __half22float2(h0), f1 = __half22float2(h1);
        float2 f2 = __half22float2(h2a), f3 = __half22float2(h3);
        float4* sp4 = (float4*)&spart[warp * ED + lane * 8];
        sp4[0] = make_float4(f0.x, f0.y, f1.x, f1.y);
        sp4[1] = make_float4(f2.x, f2.y, f3.x, f3.y);
    }
    __syncthreads();
    {
        int ch = tid;
        float r = spart[ch];
#pragma unroll
        for (int p = 1; p < 8; p++) r += spart[p * ED + ch];
        g_feats[(size_t)a * ED + ch] = r;
    }
}

// ---------------------------------------------------------------------------
// launch — inputs bound by unique element counts (order-proof)
// ---------------------------------------------------------------------------
extern "C" void kernel_launch(void* const* d_in, const int* in_sizes, int n_in,
                              void* d_out, int out_size) {
    const float* inst = 0; const float* anchor = 0;
    const float* feat[4] = {0,0,0,0};
    const float* proj = 0; const float* wh = 0;
    const float* Wl = 0; const float* bl = 0;
    const float* Ww = 0; const float* bw = 0;
    const float* Wo = 0; const float* bo = 0;

    for (int i = 0; i < n_in; i++) {
        const float* p = (const float*)d_in[i];
        switch (in_sizes[i]) {
            case 1048576:  inst    = p; break;
            case 45056:    anchor  = p; break;
            case 17301504: feat[0] = p; break;
            case 4325376:  feat[1] = p; break;
            case 1081344:  feat[2] = p; break;
            case 270336:   feat[3] = p; break;
            case 96:       proj    = p; break;
            case 12:       wh      = p; break;
            case 4608:     Wl      = p; break;
            case 18:       bl      = p; break;
            case 638976:   Ww      = p; break;
            case 2496:     bw      = p; break;
            case 65536:    Wo      = p; break;
            case 256:      bo      = p; break;
            default: break;
        }
    }
    float* out = (float*)d_out;

    // 1) transposes + fp8 convert
    const int HWs[4] = {64 * 176, 32 * 88, 16 * 44, 8 * 22};
    const unsigned LBs[4] = {0u, 17301504u, 21626880u, 22708224u};
    for (int l = 0; l < 4; l++) {
        dim3 grid((HWs[l] + 31) / 32, ED / 32, NC);
        dim3 block(32, 8);
        transpose_chw_hwc<<<grid, block>>>(feat[l], LBs[l], HWs[l]);
    }

    // 2) per-anchor setup
    setup_kernel<<<NA, 128>>>(inst, anchor, proj, wh, Wl, bl);

    // 3) weight logits GEMM on tensor cores
    {
        dim3 grid(NWTS / 64, NA / 128);
        gemm_bf16_logits<<<grid, 256>>>(inst, Ww, bw);
    }

    // 4) fused softmax + compacted aggregation (fp8 features, half2 MAC)
    agg_kernel<<<NA, 256>>>();

    // 5) output GEMM: g_feats @ Wo + bo + inst -> d_out
    {
        dim3 grid(ED / 64, NA / 128);
        sgemm_kernel<<<grid, 256>>>(nullptr, Wo, out, NA, ED, ED, bo, inst, 2);
    }
}

// round 11
// speedup vs baseline: 2.8922x; 1.0299x over previous
#include <cuda_runtime.h>
#include <cuda_fp16.h>
#include <cuda_bf16.h>
#include <cuda_fp8.h>
#include <math.h>
#include <stdint.h>

// ---------------------------------------------------------------------------
// Problem constants (fixed by the reference)
// ---------------------------------------------------------------------------
#define NA        4096
#define ED        256      // EMBED_DIMS
#define NG        8        // NUM_GROUPS
#define GD        32       // GROUP_DIMS
#define NL        4        // NUM_LEVELS
#define NC        6        // NUM_CAMS
#define NPT       13       // NUM_PTS (7 fixed + 6 learnable)
#define NSAMP     312      // NC*NL*NPT
#define NSAMPP    313      // padded (bank destagger)
#define NWTS      2496     // NSAMP*NG
#define MAXCOR    1280     // >= NSAMP*4

// level dims
__constant__ int   c_LW[4] = {176, 88, 44, 22};
__constant__ int   c_LH[4] = {64, 32, 16, 8};
__constant__ unsigned c_LB[4] = {0u, 17301504u, 21626880u, 22708224u};  // byte offsets (1B/elem)

__constant__ float c_fix[21] = {
    0.f,0.f,0.f,  0.45f,0.f,0.f,  -0.45f,0.f,0.f,
    0.f,0.45f,0.f, 0.f,-0.45f,0.f, 0.f,0.f,0.45f, 0.f,0.f,-0.45f
};

// ---------------------------------------------------------------------------
// Scratch (static __device__ — device-code references ONLY; host-side address
// of a __device__ symbol is the host shadow and silently "works" via ATS).
// ---------------------------------------------------------------------------
__device__ __align__(16) unsigned char g_f8[22978560]; // 4 levels, NHWC, fp8 e4m3
__device__ float  g_logits[NA * NWTS];      // weight logits (softmaxed in agg)
__device__ float  g_p2d[NA * NPT * NC * 2]; // projected points
__device__ float  g_feats[NA * ED];         // aggregated features

// ---------------------------------------------------------------------------
// 1) CHW -> HWC transpose + fp32->fp8(e4m3) convert (per level).
// ---------------------------------------------------------------------------
__global__ void transpose_chw_hwc(const float* __restrict__ src, unsigned dst_base, int HW) {
    __shared__ float tile[32][33];
    int cam = blockIdx.z;
    int hw0 = blockIdx.x * 32;
    int c0  = blockIdx.y * 32;
    const float* s = src + (size_t)cam * ED * HW;
    unsigned char* d = g_f8 + dst_base + (size_t)cam * HW * ED;
    int tx = threadIdx.x, ty = threadIdx.y;
#pragma unroll
    for (int i = 0; i < 32; i += 8) {
        int c  = c0 + ty + i;
        int hw = hw0 + tx;
        float v = (hw < HW) ? s[(size_t)c * HW + hw] : 0.f;
        tile[ty + i][tx] = v;
    }
    __syncthreads();
#pragma unroll
    for (int i = 0; i < 32; i += 8) {
        int hw = hw0 + ty + i;
        int c  = c0 + tx;
        if (hw < HW)
            d[(size_t)hw * ED + c] =
                (unsigned char)__nv_cvt_float_to_fp8(tile[tx][ty + i], __NV_SATFINITE, __NV_E4M3);
    }
}

// ---------------------------------------------------------------------------
// 2) Per-anchor setup: learnable points, rotation, projection -> g_p2d
// ---------------------------------------------------------------------------
__global__ void __launch_bounds__(128) setup_kernel(
    const float* __restrict__ inst, const float* __restrict__ anchor,
    const float* __restrict__ proj, const float* __restrict__ wh,
    const float* __restrict__ Wl, const float* __restrict__ bl)
{
    int a = blockIdx.x;
    int tid = threadIdx.x;
    __shared__ float sif[ED];
    __shared__ float sscale[NPT * 3];
    __shared__ float skp[NPT * 3];
    __shared__ float sR[9];
    __shared__ float sts[6];

    const float* f = inst + (size_t)a * ED;
    sif[tid]       = f[tid];
    sif[tid + 128] = f[tid + 128];
    if (tid < 21) sscale[tid] = c_fix[tid];
    __syncthreads();

    const float* an = anchor + (size_t)a * 11;

    if (tid < 18) {
        float acc = bl[tid];
#pragma unroll 8
        for (int i = 0; i < ED; i++) acc = fmaf(sif[i], Wl[i * 18 + tid], acc);
        acc = fminf(fmaxf(acc, -9.21f), 9.21f);
        float sg = 1.f / (1.f + expf(-acc));
        sscale[21 + tid] = sg - 0.5f;
    }
    if (tid == 32) {
        float t0 = an[0], t1 = an[1], t2 = an[2];
        float s0 = an[3], s1 = an[4], s2 = an[5];
        float qw = an[6], qx = an[7], qy = an[8], qz = an[9];
        float inv = rsqrtf(qw*qw + qx*qx + qy*qy + qz*qz);
        qw *= inv; qx *= inv; qy *= inv; qz *= inv;
        float R00 = 1.f - 2.f*(qy*qy + qz*qz), R01 = 2.f*(qx*qy - qw*qz), R02 = 2.f*(qx*qz + qw*qy);
        float R10 = 2.f*(qx*qy + qw*qz), R11 = 1.f - 2.f*(qx*qx + qz*qz), R12 = 2.f*(qy*qz - qw*qx);
        float R20 = 2.f*(qx*qz - qw*qy), R21 = 2.f*(qy*qz + qw*qx), R22 = 1.f - 2.f*(qx*qx + qy*qy);
        sR[0] = R00; sR[1] = R10; sR[2] = R20;
        sR[3] = R01; sR[4] = R11; sR[5] = R21;
        sR[6] = R02; sR[7] = R12; sR[8] = R22;
        sts[0] = t0; sts[1] = t1; sts[2] = t2;
        sts[3] = s0; sts[4] = s1; sts[5] = s2;
    }
    __syncthreads();
    if (tid < NPT) {
        float v0 = sscale[tid*3+0] * sts[3];
        float v1 = sscale[tid*3+1] * sts[4];
        float v2 = sscale[tid*3+2] * sts[5];
        skp[tid*3+0] = sR[0]*v0 + sR[1]*v1 + sR[2]*v2 + sts[0];
        skp[tid*3+1] = sR[3]*v0 + sR[4]*v1 + sR[5]*v2 + sts[1];
        skp[tid*3+2] = sR[6]*v0 + sR[7]*v1 + sR[8]*v2 + sts[2];
    }
    __syncthreads();
    if (tid < NPT * NC) {
        int pt = tid / NC, cam = tid % NC;
        float x = skp[pt*3+0], y = skp[pt*3+1], z = skp[pt*3+2];
        const float* P = proj + cam * 16;
        float px = P[0]*x + P[1]*y + P[2]*z  + P[3];
        float py = P[4]*x + P[5]*y + P[6]*z  + P[7];
        float pz = P[8]*x + P[9]*y + P[10]*z + P[11];
        pz = fmaxf(pz, 1e-5f);
        float u = (px / pz) / wh[cam*2+0];
        float v = (py / pz) / wh[cam*2+1];
        u = fminf(fmaxf(u, 0.f), 0.9999f);
        v = fminf(fmaxf(v, 0.f), 0.9999f);
        g_p2d[((size_t)a * (NPT*NC) + tid) * 2 + 0] = u;
        g_p2d[((size_t)a * (NPT*NC) + tid) * 2 + 1] = v;
    }
}

// ---------------------------------------------------------------------------
// 3) Logits GEMM on tensor cores: g_logits = inst @ Ww + bw
// ---------------------------------------------------------------------------
__global__ void __launch_bounds__(256) gemm_bf16_logits(
    const float* __restrict__ A, const float* __restrict__ Bm,
    const float* __restrict__ bias)
{
    float* C = g_logits;
    const int N = NWTS, K = ED;
    __shared__ __nv_bfloat16 As[128][72];
    __shared__ __nv_bfloat16 Bst[64][72];

    int tid = threadIdx.x;
    int lane = tid & 31, w = tid >> 5;
    int wm = w & 3, wn = w >> 2;
    int m0 = blockIdx.y * 128, n0 = blockIdx.x * 64;
    int g = lane >> 2, t = lane & 3;

    float d[2][4][4];
#pragma unroll
    for (int mt = 0; mt < 2; mt++)
#pragma unroll
        for (int nt = 0; nt < 4; nt++)
#pragma unroll
            for (int r = 0; r < 4; r++) d[mt][nt][r] = 0.f;

    for (int k0 = 0; k0 < K; k0 += 64) {
#pragma unroll
        for (int i = 0; i < 32; i++) {
            int e = i * 256 + tid;
            int row = e >> 6, kk = e & 63;
            As[row][kk] = __float2bfloat16(A[(size_t)(m0 + row) * K + k0 + kk]);
        }
#pragma unroll
        for (int i = 0; i < 16; i++) {
            int e = i * 256 + tid;
            int kk = e >> 6, n = e & 63;
            Bst[n][kk] = __float2bfloat16(Bm[(size_t)(k0 + kk) * N + n0 + n]);
        }
        __syncthreads();
#pragma unroll
        for (int ks = 0; ks < 4; ks++) {
            int kb = ks * 16;
            unsigned a[2][4], b[4][2];
#pragma unroll
            for (int mt = 0; mt < 2; mt++) {
                int rb = wm * 32 + mt * 16;
                a[mt][0] = *(const unsigned*)&As[rb + g][kb + 2 * t];
                a[mt][1] = *(const unsigned*)&As[rb + g + 8][kb + 2 * t];
                a[mt][2] = *(const unsigned*)&As[rb + g][kb + 2 * t + 8];
                a[mt][3] = *(const unsigned*)&As[rb + g + 8][kb + 2 * t + 8];
            }
#pragma unroll
            for (int nt = 0; nt < 4; nt++) {
                int cb = wn * 32 + nt * 8;
                b[nt][0] = *(const unsigned*)&Bst[cb + g][kb + 2 * t];
                b[nt][1] = *(const unsigned*)&Bst[cb + g][kb + 2 * t + 8];
            }
#pragma unroll
            for (int mt = 0; mt < 2; mt++)
#pragma unroll
                for (int nt = 0; nt < 4; nt++)
                    asm volatile(
                        "mma.sync.aligned.m16n8k16.row.col.f32.bf16.bf16.f32 "
                        "{%0,%1,%2,%3}, {%4,%5,%6,%7}, {%8,%9}, {%0,%1,%2,%3};"
                        : "+f"(d[mt][nt][0]), "+f"(d[mt][nt][1]),
                          "+f"(d[mt][nt][2]), "+f"(d[mt][nt][3])
                        : "r"(a[mt][0]), "r"(a[mt][1]), "r"(a[mt][2]), "r"(a[mt][3]),
                          "r"(b[nt][0]), "r"(b[nt][1]));
        }
        __syncthreads();
    }
#pragma unroll
    for (int mt = 0; mt < 2; mt++) {
        int rb = m0 + wm * 32 + mt * 16;
#pragma unroll
        for (int nt = 0; nt < 4; nt++) {
            int n = n0 + wn * 32 + nt * 8 + 2 * t;
            float b0 = bias[n], b1 = bias[n + 1];
            C[(size_t)(rb + g) * N + n]         = d[mt][nt][0] + b0;
            C[(size_t)(rb + g) * N + n + 1]     = d[mt][nt][1] + b1;
            C[(size_t)(rb + g + 8) * N + n]     = d[mt][nt][2] + b0;
            C[(size_t)(rb + g + 8) * N + n + 1] = d[mt][nt][3] + b1;
        }
    }
}

// ---------------------------------------------------------------------------
// 5) Out GEMM (f32x2 packed FMA): d_out = g_feats @ Wo + bo + inst
// ---------------------------------------------------------------------------
__global__ void __launch_bounds__(256) sgemm_kernel(
    const float* __restrict__ A, const float* __restrict__ B, float* __restrict__ C,
    int M, int N, int K, const float* __restrict__ bias, const float* __restrict__ res,
    int mode)
{
    if (mode == 2) A = g_feats;

    const int BM = 128, BN = 64, BK = 16;
    __shared__ float2 Asd[BK][BM + 2];
    __shared__ float  Bs[BK][BN];
    int tid = threadIdx.x;
    int tx = tid & 15, ty = tid >> 4;
    int m0 = blockIdx.y * BM, n0 = blockIdx.x * BN;

    unsigned long long acc[8][2];
#pragma unroll
    for (int x = 0; x < 8; x++) { acc[x][0] = 0ull; acc[x][1] = 0ull; }

    for (int k0 = 0; k0 < K; k0 += BK) {
#pragma unroll
        for (int i = 0; i < 8; i++) {
            int e = tid + i * 256;
            int m = e >> 4, kk = e & 15;
            float v = A[(size_t)(m0 + m) * K + k0 + kk];
            Asd[kk][m] = make_float2(v, v);
        }
#pragma unroll
        for (int i = 0; i < 4; i++) {
            int e = tid + i * 256;
            int kk = e >> 6, n = e & 63;
            Bs[kk][n] = B[(size_t)(k0 + kk) * N + n0 + n];
        }
        __syncthreads();
#pragma unroll
        for (int kk = 0; kk < BK; kk++) {
            unsigned long long av[8], bv[2];
            const ulonglong2* ap = (const ulonglong2*)&Asd[kk][ty * 8];
            ulonglong2 t;
            t = ap[0]; av[0] = t.x; av[1] = t.y;
            t = ap[1]; av[2] = t.x; av[3] = t.y;
            t = ap[2]; av[4] = t.x; av[5] = t.y;
            t = ap[3]; av[6] = t.x; av[7] = t.y;
            ulonglong2 bq = *(const ulonglong2*)&Bs[kk][tx * 4];
            bv[0] = bq.x; bv[1] = bq.y;
#pragma unroll
            for (int x = 0; x < 8; x++) {
                asm("fma.rn.f32x2 %0, %1, %2, %0;" : "+l"(acc[x][0]) : "l"(av[x]), "l"(bv[0]));
                asm("fma.rn.f32x2 %0, %1, %2, %0;" : "+l"(acc[x][1]) : "l"(av[x]), "l"(bv[1]));
            }
        }
        __syncthreads();
    }
#pragma unroll
    for (int x = 0; x < 8; x++) {
        int m = m0 + ty * 8 + x;
#pragma unroll
        for (int y = 0; y < 2; y++) {
            unsigned long long u = acc[x][y];
            float v0 = __uint_as_float((unsigned)u);
            float v1 = __uint_as_float((unsigned)(u >> 32));
            int n = n0 + tx * 4 + y * 2;
            if (bias) { v0 += bias[n]; v1 += bias[n + 1]; }
            if (res)  { v0 += res[(size_t)m * N + n]; v1 += res[(size_t)m * N + n + 1]; }
            C[(size_t)m * N + n]     = v0;
            C[(size_t)m * N + n + 1] = v1;
        }
    }
}

// ---------------------------------------------------------------------------
// per-sample bilinear corner metadata (shared by count & fill passes)
// ---------------------------------------------------------------------------
struct Corners {
    unsigned o[4];   // uint2-unit offsets (8 fp8 bytes per unit)
    float    w[4];   // bilinear weights (0 if invalid)
};

__device__ __forceinline__ Corners corner_meta(float2 p, int s) {
    int cam = s / (NL * NPT);
    int rr  = s % (NL * NPT);
    int lvl = rr / NPT;
    Corners r;
    int W = c_LW[lvl], H = c_LH[lvl];
    float x = p.x * (float)W - 0.5f;
    float y = p.y * (float)H - 0.5f;
    float xf = floorf(x), yf = floorf(y);
    float wx = x - xf, wy = y - yf;
    int x0 = (int)xf, y0 = (int)yf;
    int x1 = x0 + 1, y1 = y0 + 1;
    bool vx0 = (x0 >= 0) & (x0 < W);
    bool vx1 = (x1 >= 0) & (x1 < W);
    bool vy0 = (y0 >= 0) & (y0 < H);
    bool vy1 = (y1 >= 0) & (y1 < H);
    r.w[0] = (vx0 && vy0) ? (1.f - wx) * (1.f - wy) : 0.f;
    r.w[1] = (vx1 && vy0) ? wx * (1.f - wy) : 0.f;
    r.w[2] = (vx0 && vy1) ? (1.f - wx) * wy : 0.f;
    r.w[3] = (vx1 && vy1) ? wx * wy : 0.f;
    int x0c = min(max(x0, 0), W - 1), x1c = min(max(x1, 0), W - 1);
    int y0c = min(max(y0, 0), H - 1), y1c = min(max(y1, 0), H - 1);
    unsigned lb = c_LB[lvl];
    unsigned rowb = (unsigned)(cam * H);
    // byte offset = lb + texel*256; uint2 units = >>3
    r.o[0] = (lb + ((rowb + (unsigned)y0c) * (unsigned)W + (unsigned)x0c) * 256u) >> 3;
    r.o[1] = (lb + ((rowb + (unsigned)y0c) * (unsigned)W + (unsigned)x1c) * 256u) >> 3;
    r.o[2] = (lb + ((rowb + (unsigned)y1c) * (unsigned)W + (unsigned)x0c) * 256u) >> 3;
    r.o[3] = (lb + ((rowb + (unsigned)y1c) * (unsigned)W + (unsigned)x1c) * 256u) >> 3;
    return r;
}

// ---------------------------------------------------------------------------
// 4) Fused softmax + compacted bilinear aggregation (fp8 features, half2 MAC).
//    R9 hot-loop layout (warp-per-corner, uint2/lane); flist packed to 8B/entry
//    (smem 42KB -> 32KB/block: +2 resident blocks/SM for latency hiding).
// ---------------------------------------------------------------------------
__global__ void __launch_bounds__(256) agg_kernel() {
    int a = blockIdx.x;
    int tid = threadIdx.x;
    int lane = tid & 31, warp = tid >> 5;

    __shared__ float  sw[NG * NSAMPP];            // softmaxed weights, [g][s]
    __shared__ float2 sp2[NPT * NC];
    __shared__ __align__(8) uint2 flist[MAXCOR];  // (off8, s<<16 | w_half)
    __shared__ int scnt[320];
    __shared__ int sbase[NSAMP];
    __shared__ int sT;
    __shared__ __align__(16) float spart[8 * ED];

    // load logits transposed: memory col = s*NG+g -> sw[g*NSAMPP+s]
    const float* lrow = g_logits + (size_t)a * NWTS;
    for (int i = tid; i < NWTS; i += 256) {
        int s = i >> 3, g = i & 7;
        sw[g * NSAMPP + s] = lrow[i];
    }
    if (tid < NPT * NC) sp2[tid] = ((const float2*)g_p2d)[(size_t)a * (NPT*NC) + tid];
    if (tid >= NSAMP && tid < 320) scnt[tid] = 0;
    __syncthreads();

    // per-group softmax over 312 entries (warp g handles group g; conflict-free)
    {
        float* swg = sw + warp * NSAMPP;
        float m = -1e30f;
        for (int i = lane; i < NSAMP; i += 32) m = fmaxf(m, swg[i]);
#pragma unroll
        for (int o = 16; o > 0; o >>= 1) m = fmaxf(m, __shfl_xor_sync(0xffffffffu, m, o));
        float ssum = 0.f;
        for (int i = lane; i < NSAMP; i += 32) {
            float e = __expf(swg[i] - m);
            swg[i] = e;
            ssum += e;
        }
#pragma unroll
        for (int o = 16; o > 0; o >>= 1) ssum += __shfl_xor_sync(0xffffffffu, ssum, o);
        float inv = 1.f / ssum;
        for (int i = lane; i < NSAMP; i += 32) swg[i] *= inv;
    }

    // pass 1: per-sample valid-corner counts
    for (int s = tid; s < NSAMP; s += 256) {
        int pt = (s % (NL * NPT)) % NPT, cam = s / (NL * NPT);
        Corners cr = corner_meta(sp2[pt * NC + cam], s);
        scnt[s] = (cr.w[0] != 0.f) + (cr.w[1] != 0.f) + (cr.w[2] != 0.f) + (cr.w[3] != 0.f);
    }
    __syncthreads();

    // deterministic exclusive scan over 312 counts
    if (tid < 32) {
        int l = tid;
        int tot = 0;
#pragma unroll
        for (int k = 0; k < 10; k++) {
            int s = l * 10 + k;
            tot += (s < NSAMP) ? scnt[s] : 0;
        }
        int inc = tot;
#pragma unroll
        for (int o = 1; o < 32; o <<= 1) {
            int v = __shfl_up_sync(0xffffffffu, inc, o);
            if (l >= o) inc += v;
        }
        int run = inc - tot;
#pragma unroll
        for (int k = 0; k < 10; k++) {
            int s = l * 10 + k;
            if (s < NSAMP) { sbase[s] = run; run += scnt[s]; }
        }
        if (l == 31) sT = run;
    }
    __syncthreads();

    // pass 2: fill compacted corner list (weight stored as half)
    for (int s = tid; s < NSAMP; s += 256) {
        int pt = (s % (NL * NPT)) % NPT, cam = s / (NL * NPT);
        Corners cr = corner_meta(sp2[pt * NC + cam], s);
        int b = sbase[s];
        unsigned shi = ((unsigned)s) << 16;
#pragma unroll
        for (int k = 0; k < 4; k++) {
            if (cr.w[k] != 0.f) {
                unsigned wbits = (unsigned)__half_as_ushort(__float2half_rn(cr.w[k]));
                flist[b] = make_uint2(cr.o[k], shi | wbits);
                b++;
            }
        }
    }
    __syncthreads();

    const int T = sT;
    int g = lane >> 2;                    // group of this 8-channel slab
    const float* swg = sw + g * NSAMPP;
    __half2 hz = __float2half2_rn(0.f);
    __half2 h0 = hz, h1 = hz, h2a = hz, h3 = hz;
    const uint2* __restrict__ F8 = (const uint2*)g_f8;
#pragma unroll 4
    for (int j = warp; j < T; j += 8) {
        uint2 e = flist[j];                                   // broadcast LDS.64
        float w = swg[e.y >> 16] *
                  __half2float(__ushort_as_half((unsigned short)(e.y & 0xffffu)));
        __half2 wh = __float2half2_rn(w);
        uint2 u = __ldg(F8 + e.x + lane);
        __half2_raw r0 = __nv_cvt_fp8x2_to_halfraw2((__nv_fp8x2_storage_t)(u.x & 0xffffu), __NV_E4M3);
        __half2_raw r1 = __nv_cvt_fp8x2_to_halfraw2((__nv_fp8x2_storage_t)(u.x >> 16), __NV_E4M3);
        __half2_raw r2 = __nv_cvt_fp8x2_to_halfraw2((__nv_fp8x2_storage_t)(u.y & 0xffffu), __NV_E4M3);
        __half2_raw r3 = __nv_cvt_fp8x2_to_halfraw2((__nv_fp8x2_storage_t)(u.y >> 16), __NV_E4M3);
        h0  = __hfma2(wh, *reinterpret_cast<__half2*>(&r0), h0);
        h1  = __hfma2(wh, *reinterpret_cast<__half2*>(&r1), h1);
        h2a = __hfma2(wh, *reinterpret_cast<__half2*>(&r2), h2a);
        h3  = __hfma2(wh, *reinterpret_cast<__half2*>(&r3), h3);
    }
    {
        float2 f0 = __half22float2(h0), f1 = __half22float2(h1);
        float2 f2 = __half22float2(h2a), f3 = __half22float2(h3);
        float4* sp4 = (float4*)&spart[warp * ED + lane * 8];
        sp4[0] = make_float4(f0.x, f0.y, f1.x, f1.y);
        sp4[1] = make_float4(f2.x, f2.y, f3.x, f3.y);
    }
    __syncthreads();
    {
        int ch = tid;
        float r = spart[ch];
#pragma unroll
        for (int p = 1; p < 8; p++) r += spart[p * ED + ch];
        g_feats[(size_t)a * ED + ch] = r;
    }
}

// ---------------------------------------------------------------------------
// launch — inputs bound by unique element counts (order-proof); single stream
// ---------------------------------------------------------------------------
extern "C" void kernel_launch(void* const* d_in, const int* in_sizes, int n_in,
                              void* d_out, int out_size) {
    const float* inst = 0; const float* anchor = 0;
    const float* feat[4] = {0,0,0,0};
    const float* proj = 0; const float* wh = 0;
    const float* Wl = 0; const float* bl = 0;
    const float* Ww = 0; const float* bw = 0;
    const float* Wo = 0; const float* bo = 0;

    for (int i = 0; i < n_in; i++) {
        const float* p = (const float*)d_in[i];
        switch (in_sizes[i]) {
            case 1048576:  inst    = p; break;
            case 45056:    anchor  = p; break;
            case 17301504: feat[0] = p; break;
            case 4325376:  feat[1] = p; break;
            case 1081344:  feat[2] = p; break;
            case 270336:   feat[3] = p; break;
            case 96:       proj    = p; break;
            case 12:       wh      = p; break;
            case 4608:     Wl      = p; break;
            case 18:       bl      = p; break;
            case 638976:   Ww      = p; break;
            case 2496:     bw      = p; break;
            case 65536:    Wo      = p; break;
            case 256:      bo      = p; break;
            default: break;
        }
    }
    float* out = (float*)d_out;

    // 1) transposes + fp8 convert
    const int HWs[4] = {64 * 176, 32 * 88, 16 * 44, 8 * 22};
    const unsigned LBs[4] = {0u, 17301504u, 21626880u, 22708224u};
    for (int l = 0; l < 4; l++) {
        dim3 grid((HWs[l] + 31) / 32, ED / 32, NC);
        dim3 block(32, 8);
        transpose_chw_hwc<<<grid, block>>>(feat[l], LBs[l], HWs[l]);
    }

    // 2) per-anchor setup
    setup_kernel<<<NA, 128>>>(inst, anchor, proj, wh, Wl, bl);

    // 3) weight logits GEMM on tensor cores
    {
        dim3 grid(NWTS / 64, NA / 128);
        gemm_bf16_logits<<<grid, 256>>>(inst, Ww, bw);
    }

    // 4) fused softmax + compacted aggregation (fp8 features)
    agg_kernel<<<NA, 256>>>();

    // 5) output GEMM: g_feats @ Wo + bo + inst -> d_out
    {
        dim3 grid(ED / 64, NA / 128);
        sgemm_kernel<<<grid, 256>>>(nullptr, Wo, out, NA, ED, ED, bo, inst, 2);
    }
}